// round 2
// baseline (speedup 1.0000x reference)
#include <cuda_runtime.h>
#include <math.h>
#include <stdint.h>

// Problem constants (fixed by setup_inputs): B=8, S=2048, D=512
#define BB 8
#define SS 2048
#define DD 512
#define MM (BB*SS)          // 16384 token rows
#define EPS_Q 1e-5f
#define SCORE_SCALE 0.35355339059327373f   // 8^-0.5

// ---------------- scratch (static __device__, no runtime alloc) ----------------
__device__ float g_wmean[3];
__device__ float g_wq[3][DD*DD];              // dequantized ternary weights, 3 MB
__device__ float g_xq[MM*DD];                 // dequantized int8 activations, 33.5 MB
__device__ float g_q[MM*DD];
__device__ float g_k[MM*DD];
__device__ float g_v[MM*DD];
__device__ float g_scores[(size_t)BB*SS*SS];  // 134 MB

// ---------------- weight mean(|w|) ----------------
__global__ void wmean_kernel(const float* __restrict__ Wq,
                             const float* __restrict__ Wk,
                             const float* __restrict__ Wv) {
    const float* W = (blockIdx.x == 0) ? Wq : (blockIdx.x == 1) ? Wk : Wv;
    __shared__ float red[256];
    float s = 0.f;
    for (int i = threadIdx.x; i < DD*DD; i += 256) s += fabsf(W[i]);
    red[threadIdx.x] = s;
    __syncthreads();
    for (int o = 128; o > 0; o >>= 1) {
        if (threadIdx.x < o) red[threadIdx.x] += red[threadIdx.x + o];
        __syncthreads();
    }
    if (threadIdx.x == 0)
        g_wmean[blockIdx.x] = fmaxf(red[0] / (float)(DD*DD), EPS_Q);
}

// ---------------- weight ternary quant (dequantized) ----------------
__global__ void wquant_kernel(const float* __restrict__ Wq,
                              const float* __restrict__ Wk,
                              const float* __restrict__ Wv) {
    int i = blockIdx.x * blockDim.x + threadIdx.x;
    if (i >= 3*DD*DD) return;
    int w = i / (DD*DD), j = i - w*(DD*DD);
    const float* W = (w == 0) ? Wq : (w == 1) ? Wk : Wv;
    float mean = g_wmean[w];
    float scale = 1.0f / mean;                 // reference computes reciprocal then multiplies
    float t = rintf(W[j] * scale);             // rintf = round half to even, matches jnp.round
    t = fminf(fmaxf(t, -1.f), 1.f);
    g_wq[w][j] = t * mean;
}

// ---------------- activation per-token int8 quant (dequantized) ----------------
__global__ void actquant_kernel(const float* __restrict__ x) {
    int row = blockIdx.x;                       // 16384 rows
    const float* px = x + (size_t)row * DD;
    float vals[4];
    float m = 0.f;
    #pragma unroll
    for (int u = 0; u < 4; u++) {
        vals[u] = px[threadIdx.x + u*128];
        m = fmaxf(m, fabsf(vals[u]));
    }
    __shared__ float red[128];
    red[threadIdx.x] = m;
    __syncthreads();
    for (int o = 64; o > 0; o >>= 1) {
        if (threadIdx.x < o) red[threadIdx.x] = fmaxf(red[threadIdx.x], red[threadIdx.x + o]);
        __syncthreads();
    }
    float scale = 127.0f / fmaxf(red[0], EPS_Q);
    #pragma unroll
    for (int u = 0; u < 4; u++) {
        float v = rintf(vals[u] * scale);
        v = fminf(fmaxf(v, -128.f), 127.f);
        g_xq[(size_t)row*DD + threadIdx.x + u*128] = v / scale;
    }
}

// ---------------- tiled GEMM core: 64x64 tile, KT=16, 256 thr, 4x4 microtile ----
// NT form: C[i][j] = sum_k A[i*K+k] * B[j*K+k]
__device__ __forceinline__ void gemm_tile_nt(const float* __restrict__ A,
                                             const float* __restrict__ B,
                                             int K, int row0, int col0,
                                             float acc[4][4]) {
    __shared__ float As[16][64];
    __shared__ float Bs[16][64];
    const int tid = threadIdx.x;
    const int ty = tid >> 4, tx = tid & 15;
    const int li = tid >> 2, lk = (tid & 3) << 2;
    for (int k0 = 0; k0 < K; k0 += 16) {
        float4 a = *(const float4*)(A + (size_t)(row0 + li) * K + k0 + lk);
        float4 b = *(const float4*)(B + (size_t)(col0 + li) * K + k0 + lk);
        As[lk+0][li] = a.x; As[lk+1][li] = a.y; As[lk+2][li] = a.z; As[lk+3][li] = a.w;
        Bs[lk+0][li] = b.x; Bs[lk+1][li] = b.y; Bs[lk+2][li] = b.z; Bs[lk+3][li] = b.w;
        __syncthreads();
        #pragma unroll
        for (int kk = 0; kk < 16; kk++) {
            float4 av = *(const float4*)&As[kk][ty << 2];
            float4 bv = *(const float4*)&Bs[kk][tx << 2];
            acc[0][0] += av.x*bv.x; acc[0][1] += av.x*bv.y; acc[0][2] += av.x*bv.z; acc[0][3] += av.x*bv.w;
            acc[1][0] += av.y*bv.x; acc[1][1] += av.y*bv.y; acc[1][2] += av.y*bv.z; acc[1][3] += av.y*bv.w;
            acc[2][0] += av.z*bv.x; acc[2][1] += av.z*bv.y; acc[2][2] += av.z*bv.z; acc[2][3] += av.z*bv.w;
            acc[3][0] += av.w*bv.x; acc[3][1] += av.w*bv.y; acc[3][2] += av.w*bv.z; acc[3][3] += av.w*bv.w;
        }
        __syncthreads();
    }
}

// ---------------- QKV projection: y = xq @ wq^T ----------------
__global__ void qkv_gemm_kernel() {
    int w = blockIdx.z;
    const float* A = g_xq;
    const float* B = g_wq[w];
    float* C = (w == 0) ? g_q : (w == 1) ? g_k : g_v;
    int row0 = blockIdx.y * 64, col0 = blockIdx.x * 64;
    float acc[4][4] = {};
    gemm_tile_nt(A, B, DD, row0, col0, acc);
    const int ty = threadIdx.x >> 4, tx = threadIdx.x & 15;
    #pragma unroll
    for (int r = 0; r < 4; r++)
        #pragma unroll
        for (int c = 0; c < 4; c++)
            C[(size_t)(row0 + ty*4 + r) * DD + col0 + tx*4 + c] = acc[r][c];
}

// ---------------- scores = (q @ k^T) * SCALE with causal mask ----------------
__global__ void scores_kernel() {
    int b = blockIdx.z;
    int row0 = blockIdx.y * 64, col0 = blockIdx.x * 64;
    float* C = g_scores + (size_t)b * SS * SS;
    const int ty = threadIdx.x >> 4, tx = threadIdx.x & 15;
    const float NEG_INF = __int_as_float(0xff800000);
    if (col0 > row0 + 63) {   // tile fully above diagonal: masked, no compute
        #pragma unroll
        for (int r = 0; r < 4; r++)
            #pragma unroll
            for (int c = 0; c < 4; c++)
                C[(size_t)(row0 + ty*4 + r) * SS + col0 + tx*4 + c] = NEG_INF;
        return;
    }
    const float* A = g_q + (size_t)b * SS * DD;
    const float* B = g_k + (size_t)b * SS * DD;
    float acc[4][4] = {};
    gemm_tile_nt(A, B, DD, row0, col0, acc);
    #pragma unroll
    for (int r = 0; r < 4; r++) {
        int i = row0 + ty*4 + r;
        #pragma unroll
        for (int c = 0; c < 4; c++) {
            int j = col0 + tx*4 + c;
            C[(size_t)i * SS + j] = (j <= i) ? acc[r][c] * SCORE_SCALE : NEG_INF;
        }
    }
}

// ---------------- row softmax over 2048 (masked entries are -inf) ----------------
__global__ void softmax_kernel() {
    size_t row = blockIdx.x;                // 0..16383
    float* p = g_scores + row * SS;
    __shared__ float red[256];
    int t = threadIdx.x;
    float m = __int_as_float(0xff800000);
    for (int j = t; j < SS; j += 256) m = fmaxf(m, p[j]);
    red[t] = m; __syncthreads();
    for (int o = 128; o > 0; o >>= 1) {
        if (t < o) red[t] = fmaxf(red[t], red[t + o]);
        __syncthreads();
    }
    float mx = red[0];
    __syncthreads();
    float s = 0.f;
    for (int j = t; j < SS; j += 256) {
        float e = expf(p[j] - mx);
        p[j] = e;
        s += e;
    }
    red[t] = s; __syncthreads();
    for (int o = 128; o > 0; o >>= 1) {
        if (t < o) red[t] += red[t + o];
        __syncthreads();
    }
    float inv = 1.0f / red[0];
    for (int j = t; j < SS; j += 256) p[j] *= inv;
}

// ---------------- out = attn @ v  (NN gemm, causal k-range skip) ----------------
__global__ void av_kernel(float* __restrict__ out) {
    int b = blockIdx.z;
    int row0 = blockIdx.y * 64, col0 = blockIdx.x * 64;
    const float* A = g_scores + (size_t)b * SS * SS;   // attn, row-major [SS, SS]
    const float* B = g_v + (size_t)b * SS * DD;        // [SS, DD] row-major
    float* C = out + (size_t)b * SS * DD;
    __shared__ float As[16][64];
    __shared__ float Bs[16][64];
    const int tid = threadIdx.x;
    const int ty = tid >> 4, tx = tid & 15;
    const int li = tid >> 2, lk = (tid & 3) << 2;      // A loader
    const int bk = tid >> 4, bj = (tid & 15) << 2;     // B loader
    float acc[4][4] = {};
    int kend = row0 + 64;                              // attn rows are zero beyond the diagonal
    if (kend > SS) kend = SS;
    for (int k0 = 0; k0 < kend; k0 += 16) {
        float4 a = *(const float4*)(A + (size_t)(row0 + li) * SS + k0 + lk);
        As[lk+0][li] = a.x; As[lk+1][li] = a.y; As[lk+2][li] = a.z; As[lk+3][li] = a.w;
        float4 bv = *(const float4*)(B + (size_t)(k0 + bk) * DD + col0 + bj);
        *(float4*)&Bs[bk][bj] = bv;
        __syncthreads();
        #pragma unroll
        for (int kk = 0; kk < 16; kk++) {
            float4 av = *(const float4*)&As[kk][ty << 2];
            float4 bv2 = *(const float4*)&Bs[kk][tx << 2];
            acc[0][0] += av.x*bv2.x; acc[0][1] += av.x*bv2.y; acc[0][2] += av.x*bv2.z; acc[0][3] += av.x*bv2.w;
            acc[1][0] += av.y*bv2.x; acc[1][1] += av.y*bv2.y; acc[1][2] += av.y*bv2.z; acc[1][3] += av.y*bv2.w;
            acc[2][0] += av.z*bv2.x; acc[2][1] += av.z*bv2.y; acc[2][2] += av.z*bv2.z; acc[2][3] += av.z*bv2.w;
            acc[3][0] += av.w*bv2.x; acc[3][1] += av.w*bv2.y; acc[3][2] += av.w*bv2.z; acc[3][3] += av.w*bv2.w;
        }
        __syncthreads();
    }
    #pragma unroll
    for (int r = 0; r < 4; r++)
        #pragma unroll
        for (int c = 0; c < 4; c++)
            C[(size_t)(row0 + ty*4 + r) * DD + col0 + tx*4 + c] = acc[r][c];
}

// ---------------- launch ----------------
extern "C" void kernel_launch(void* const* d_in, const int* in_sizes, int n_in,
                              void* d_out, int out_size) {
    (void)in_sizes; (void)n_in; (void)out_size;
    const float* x  = (const float*)d_in[0];
    const float* Wq = (const float*)d_in[1];
    const float* Wk = (const float*)d_in[2];
    const float* Wv = (const float*)d_in[3];
    float* out = (float*)d_out;

    wmean_kernel<<<3, 256>>>(Wq, Wk, Wv);
    wquant_kernel<<<(3*DD*DD + 255)/256, 256>>>(Wq, Wk, Wv);
    actquant_kernel<<<MM, 128>>>(x);

    dim3 gqkv(DD/64, MM/64, 3);           // (8, 256, 3)
    qkv_gemm_kernel<<<gqkv, 256>>>();

    dim3 gsc(SS/64, SS/64, BB);           // (32, 32, 8)
    scores_kernel<<<gsc, 256>>>();

    softmax_kernel<<<MM, 256>>>();

    dim3 gav(DD/64, SS/64, BB);           // (8, 32, 8)
    av_kernel<<<gav, 256>>>(out);
}

// round 4
// speedup vs baseline: 1.1323x; 1.1323x over previous
#include <cuda_runtime.h>
#include <math.h>
#include <stdint.h>

// Problem constants: B=8, S=2048, D=512
#define BB 8
#define SS 2048
#define DD 512
#define MM (BB*SS)
#define EPS_Q 1e-5f
#define SCORE_SCALE 0.35355339059327373f   // 8^-0.5

// ---------------- scratch ----------------
__device__ float g_wmean[3];
__device__ float g_wq[3][DD*DD];
__device__ float g_xq[MM*DD];
__device__ float g_q[MM*DD];
__device__ float g_k[MM*DD];
__device__ float g_v[MM*DD];
__device__ float g_scores[(size_t)BB*SS*SS];  // 134 MB

// ---------------- weight mean(|w|) ----------------
__global__ void wmean_kernel(const float* __restrict__ Wq,
                             const float* __restrict__ Wk,
                             const float* __restrict__ Wv) {
    const float* W = (blockIdx.x == 0) ? Wq : (blockIdx.x == 1) ? Wk : Wv;
    __shared__ float red[256];
    float s = 0.f;
    for (int i = threadIdx.x; i < DD*DD; i += 256) s += fabsf(W[i]);
    red[threadIdx.x] = s;
    __syncthreads();
    for (int o = 128; o > 0; o >>= 1) {
        if (threadIdx.x < o) red[threadIdx.x] += red[threadIdx.x + o];
        __syncthreads();
    }
    if (threadIdx.x == 0)
        g_wmean[blockIdx.x] = fmaxf(red[0] / (float)(DD*DD), EPS_Q);
}

// ---------------- weight ternary quant (dequantized) ----------------
__global__ void wquant_kernel(const float* __restrict__ Wq,
                              const float* __restrict__ Wk,
                              const float* __restrict__ Wv) {
    int i = blockIdx.x * blockDim.x + threadIdx.x;
    if (i >= 3*DD*DD) return;
    int w = i / (DD*DD), j = i - w*(DD*DD);
    const float* W = (w == 0) ? Wq : (w == 1) ? Wk : Wv;
    float mean = g_wmean[w];
    float scale = 1.0f / mean;
    float t = rintf(W[j] * scale);
    t = fminf(fmaxf(t, -1.f), 1.f);
    g_wq[w][j] = t * mean;
}

// ---------------- activation per-token int8 quant (dequantized) ----------------
__global__ void actquant_kernel(const float* __restrict__ x) {
    int row = blockIdx.x;
    const float* px = x + (size_t)row * DD;
    float vals[4];
    float m = 0.f;
    #pragma unroll
    for (int u = 0; u < 4; u++) {
        vals[u] = px[threadIdx.x + u*128];
        m = fmaxf(m, fabsf(vals[u]));
    }
    __shared__ float red[128];
    red[threadIdx.x] = m;
    __syncthreads();
    for (int o = 64; o > 0; o >>= 1) {
        if (threadIdx.x < o) red[threadIdx.x] = fmaxf(red[threadIdx.x], red[threadIdx.x + o]);
        __syncthreads();
    }
    float scale = 127.0f / fmaxf(red[0], EPS_Q);
    #pragma unroll
    for (int u = 0; u < 4; u++) {
        float v = rintf(vals[u] * scale);
        v = fminf(fmaxf(v, -128.f), 127.f);
        g_xq[(size_t)row*DD + threadIdx.x + u*128] = v / scale;
    }
}

// ================= 128x128x16 GEMM machinery (256 thr, 8x8 microtile) =========

// NT loaders: both A and B are K-major (row i contiguous over K)
__device__ __forceinline__ void ld_nt(const float* __restrict__ A,
                                      const float* __restrict__ B,
                                      int K, int row0, int col0, int k0,
                                      float4 pa[2], float4 pb[2], int tid) {
    #pragma unroll
    for (int l = 0; l < 2; l++) {
        int idx = tid + l*256;
        int r = idx >> 2, kq = (idx & 3) << 2;
        pa[l] = *(const float4*)(A + (size_t)(row0 + r) * K + k0 + kq);
        pb[l] = *(const float4*)(B + (size_t)(col0 + r) * K + k0 + kq);
    }
}

__device__ __forceinline__ void st_nt(float As[16][128], float Bs[16][128],
                                      const float4 pa[2], const float4 pb[2], int tid) {
    #pragma unroll
    for (int l = 0; l < 2; l++) {
        int idx = tid + l*256;
        int r = idx >> 2, kq = (idx & 3) << 2;
        As[kq+0][r] = pa[l].x; As[kq+1][r] = pa[l].y; As[kq+2][r] = pa[l].z; As[kq+3][r] = pa[l].w;
        Bs[kq+0][r] = pb[l].x; Bs[kq+1][r] = pb[l].y; Bs[kq+2][r] = pb[l].z; Bs[kq+3][r] = pb[l].w;
    }
}

__device__ __forceinline__ void mma_8x8(const float As[16][128], const float Bs[16][128],
                                        int ty8, int tx8, float acc[8][8]) {
    #pragma unroll
    for (int kk = 0; kk < 16; kk++) {
        float4 a0 = *(const float4*)&As[kk][ty8];
        float4 a1 = *(const float4*)&As[kk][ty8 + 4];
        float4 b0 = *(const float4*)&Bs[kk][tx8];
        float4 b1 = *(const float4*)&Bs[kk][tx8 + 4];
        float ar[8] = {a0.x, a0.y, a0.z, a0.w, a1.x, a1.y, a1.z, a1.w};
        float br[8] = {b0.x, b0.y, b0.z, b0.w, b1.x, b1.y, b1.z, b1.w};
        #pragma unroll
        for (int r = 0; r < 8; r++)
            #pragma unroll
            for (int c = 0; c < 8; c++)
                acc[r][c] += ar[r] * br[c];
    }
}

// full NT gemm over K with register prefetch
__device__ __forceinline__ void gemm_nt_128(const float* __restrict__ A,
                                            const float* __restrict__ B,
                                            int K, int row0, int col0,
                                            float As[16][128], float Bs[16][128],
                                            float acc[8][8]) {
    const int tid = threadIdx.x;
    const int ty8 = (tid >> 4) << 3, tx8 = (tid & 15) << 3;
    float4 pa[2], pb[2];
    ld_nt(A, B, K, row0, col0, 0, pa, pb, tid);
    st_nt(As, Bs, pa, pb, tid);
    __syncthreads();
    for (int k0 = 0; k0 < K; k0 += 16) {
        bool nxt = (k0 + 16) < K;
        if (nxt) ld_nt(A, B, K, row0, col0, k0 + 16, pa, pb, tid);
        mma_8x8(As, Bs, ty8, tx8, acc);
        __syncthreads();
        if (nxt) { st_nt(As, Bs, pa, pb, tid); __syncthreads(); }
    }
}

// ---------------- QKV projection: y = xq @ wq^T ----------------
__global__ void qkv_gemm_kernel() {
    __shared__ float As[16][128];
    __shared__ float Bs[16][128];
    int w = blockIdx.z;
    const float* B = g_wq[w];
    float* C = (w == 0) ? g_q : (w == 1) ? g_k : g_v;
    int row0 = blockIdx.y * 128, col0 = blockIdx.x * 128;
    float acc[8][8] = {};
    gemm_nt_128(g_xq, B, DD, row0, col0, As, Bs, acc);
    const int ty8 = (threadIdx.x >> 4) << 3, tx8 = (threadIdx.x & 15) << 3;
    #pragma unroll
    for (int r = 0; r < 8; r++) {
        float* p = C + (size_t)(row0 + ty8 + r) * DD + col0 + tx8;
        *(float4*)(p)     = make_float4(acc[r][0], acc[r][1], acc[r][2], acc[r][3]);
        *(float4*)(p + 4) = make_float4(acc[r][4], acc[r][5], acc[r][6], acc[r][7]);
    }
}

// ---------------- scores = (q @ k^T) * SCALE, causal; skip masked tiles --------
__global__ void scores_kernel() {
    int row0 = blockIdx.y * 128, col0 = blockIdx.x * 128;
    if (col0 > row0 + 127) return;              // fully masked: never written, never read
    __shared__ float As[16][128];
    __shared__ float Bs[16][128];
    int b = blockIdx.z;
    const float* A = g_q + (size_t)b * SS * DD;
    const float* B = g_k + (size_t)b * SS * DD;
    float* C = g_scores + (size_t)b * SS * SS;
    float acc[8][8] = {};
    gemm_nt_128(A, B, DD, row0, col0, As, Bs, acc);
    const int ty8 = (threadIdx.x >> 4) << 3, tx8 = (threadIdx.x & 15) << 3;
    const float NEG_INF = __int_as_float(0xff800000);
    #pragma unroll
    for (int r = 0; r < 8; r++) {
        int i = row0 + ty8 + r;
        float* p = C + (size_t)i * SS + col0 + tx8;
        #pragma unroll
        for (int c = 0; c < 8; c++) {
            int j = col0 + tx8 + c;
            p[c] = (j <= i) ? acc[r][c] * SCORE_SCALE : NEG_INF;
        }
    }
}

// ---------------- row softmax; only the row's 128-tile-bounded prefix ----------
__global__ void softmax_kernel() {
    size_t row = blockIdx.x;
    int ri = (int)(row & (SS - 1));
    int jend = (ri & ~127) + 128;               // av_kernel reads exactly this range
    float* p = g_scores + row * SS;
    __shared__ float red[256];
    int t = threadIdx.x;
    float m = __int_as_float(0xff800000);
    for (int j = t; j < jend; j += 256) m = fmaxf(m, p[j]);
    red[t] = m; __syncthreads();
    for (int o = 128; o > 0; o >>= 1) {
        if (t < o) red[t] = fmaxf(red[t], red[t + o]);
        __syncthreads();
    }
    float mx = red[0];
    __syncthreads();
    float s = 0.f;
    for (int j = t; j < jend; j += 256) {
        float e = expf(p[j] - mx);
        p[j] = e;
        s += e;
    }
    red[t] = s; __syncthreads();
    for (int o = 128; o > 0; o >>= 1) {
        if (t < o) red[t] += red[t + o];
        __syncthreads();
    }
    float inv = 1.0f / red[0];
    for (int j = t; j < jend; j += 256) p[j] *= inv;
}

// ---------------- out = attn @ v (NN, causal k-range skip) ----------------
__global__ void av_kernel(float* __restrict__ out) {
    __shared__ float As[16][128];
    __shared__ float Bs[16][128];
    int b = blockIdx.z;
    int row0 = blockIdx.y * 128, col0 = blockIdx.x * 128;
    const float* A = g_scores + (size_t)b * SS * SS;   // [SS, SS] row-major
    const float* B = g_v + (size_t)b * SS * DD;        // [SS, DD] row-major
    float* C = out + (size_t)b * SS * DD;
    const int tid = threadIdx.x;
    const int ty8 = (tid >> 4) << 3, tx8 = (tid & 15) << 3;
    float acc[8][8] = {};
    int kend = row0 + 128;                             // attn rows zero beyond own tile

    float4 pa[2], pb[2];
    // loader A (k-contiguous): idx -> (row idx>>2, kq idx&3)
    // loader B (n-contiguous): idx -> (k idx>>5, n4 idx&31)
    #pragma unroll
    for (int l = 0; l < 2; l++) {
        int idx = tid + l*256;
        pa[l] = *(const float4*)(A + (size_t)(row0 + (idx >> 2)) * SS + ((idx & 3) << 2));
        pb[l] = *(const float4*)(B + (size_t)(idx >> 5) * DD + col0 + ((idx & 31) << 2));
    }
    #pragma unroll
    for (int l = 0; l < 2; l++) {
        int idx = tid + l*256;
        int r = idx >> 2, kq = (idx & 3) << 2;
        As[kq+0][r] = pa[l].x; As[kq+1][r] = pa[l].y; As[kq+2][r] = pa[l].z; As[kq+3][r] = pa[l].w;
        *(float4*)&Bs[idx >> 5][(idx & 31) << 2] = pb[l];
    }
    __syncthreads();

    for (int k0 = 0; k0 < kend; k0 += 16) {
        bool nxt = (k0 + 16) < kend;
        if (nxt) {
            #pragma unroll
            for (int l = 0; l < 2; l++) {
                int idx = tid + l*256;
                pa[l] = *(const float4*)(A + (size_t)(row0 + (idx >> 2)) * SS + k0 + 16 + ((idx & 3) << 2));
                pb[l] = *(const float4*)(B + (size_t)(k0 + 16 + (idx >> 5)) * DD + col0 + ((idx & 31) << 2));
            }
        }
        mma_8x8(As, Bs, ty8, tx8, acc);
        __syncthreads();
        if (nxt) {
            #pragma unroll
            for (int l = 0; l < 2; l++) {
                int idx = tid + l*256;
                int r = idx >> 2, kq = (idx & 3) << 2;
                As[kq+0][r] = pa[l].x; As[kq+1][r] = pa[l].y; As[kq+2][r] = pa[l].z; As[kq+3][r] = pa[l].w;
                *(float4*)&Bs[idx >> 5][(idx & 31) << 2] = pb[l];
            }
            __syncthreads();
        }
    }
    #pragma unroll
    for (int r = 0; r < 8; r++) {
        float* p = C + (size_t)(row0 + ty8 + r) * DD + col0 + tx8;
        *(float4*)(p)     = make_float4(acc[r][0], acc[r][1], acc[r][2], acc[r][3]);
        *(float4*)(p + 4) = make_float4(acc[r][4], acc[r][5], acc[r][6], acc[r][7]);
    }
}

// ---------------- launch ----------------
extern "C" void kernel_launch(void* const* d_in, const int* in_sizes, int n_in,
                              void* d_out, int out_size) {
    (void)in_sizes; (void)n_in; (void)out_size;
    const float* x  = (const float*)d_in[0];
    const float* Wq = (const float*)d_in[1];
    const float* Wk = (const float*)d_in[2];
    const float* Wv = (const float*)d_in[3];
    float* out = (float*)d_out;

    wmean_kernel<<<3, 256>>>(Wq, Wk, Wv);
    wquant_kernel<<<(3*DD*DD + 255)/256, 256>>>(Wq, Wk, Wv);
    actquant_kernel<<<MM, 128>>>(x);

    dim3 gqkv(DD/128, MM/128, 3);          // (4, 128, 3)
    qkv_gemm_kernel<<<gqkv, 256>>>();

    dim3 gsc(SS/128, SS/128, BB);          // (16, 16, 8)
    scores_kernel<<<gsc, 256>>>();

    softmax_kernel<<<MM, 256>>>();

    dim3 gav(DD/128, SS/128, BB);          // (4, 16, 8)
    av_kernel<<<gav, 256>>>(out);
}

// round 6
// speedup vs baseline: 1.5559x; 1.3741x over previous
#include <cuda_runtime.h>
#include <math.h>
#include <stdint.h>

// Problem constants: B=8, S=2048, D=512
#define BB 8
#define SS 2048
#define DD 512
#define MM (BB*SS)
#define KW (DD/4)           // 128 packed int8 words per row
#define EPS_Q 1e-5f
#define SCORE_SCALE 0.35355339059327373f   // 8^-0.5

// ---------------- scratch ----------------
__device__ float g_wmean[3];
__device__ int   g_w4[3][DD*KW];              // packed ternary int8 weights
__device__ int   g_x4[MM*KW];                 // packed int8 activations
__device__ float g_xscale[MM];                // dequant multiplier per token row
__device__ float g_q[MM*DD];
__device__ float g_k[MM*DD];
__device__ float g_v[MM*DD];
__device__ float g_scores[(size_t)BB*SS*SS];  // 134 MB

// ---------------- weight mean(|w|) ----------------
__global__ void wmean_kernel(const float* __restrict__ Wq,
                             const float* __restrict__ Wk,
                             const float* __restrict__ Wv) {
    const float* W = (blockIdx.x == 0) ? Wq : (blockIdx.x == 1) ? Wk : Wv;
    __shared__ float red[256];
    float s = 0.f;
    for (int i = threadIdx.x; i < DD*DD; i += 256) s += fabsf(W[i]);
    red[threadIdx.x] = s;
    __syncthreads();
    for (int o = 128; o > 0; o >>= 1) {
        if (threadIdx.x < o) red[threadIdx.x] += red[threadIdx.x + o];
        __syncthreads();
    }
    if (threadIdx.x == 0)
        g_wmean[blockIdx.x] = fmaxf(red[0] / (float)(DD*DD), EPS_Q);
}

// ---------------- weight ternary quant -> packed int8 ----------------
__global__ void wquant_kernel(const float* __restrict__ Wq,
                              const float* __restrict__ Wk,
                              const float* __restrict__ Wv) {
    int i = blockIdx.x * blockDim.x + threadIdx.x;   // word index
    if (i >= 3*DD*KW) return;
    int w = i / (DD*KW), j = i - w*(DD*KW);          // word within matrix
    const float* W = (w == 0) ? Wq : (w == 1) ? Wk : Wv;
    float inv = 1.0f / g_wmean[w];
    float4 v = *(const float4*)(W + j*4);
    int t0 = (int)fminf(fmaxf(rintf(v.x*inv), -1.f), 1.f);
    int t1 = (int)fminf(fmaxf(rintf(v.y*inv), -1.f), 1.f);
    int t2 = (int)fminf(fmaxf(rintf(v.z*inv), -1.f), 1.f);
    int t3 = (int)fminf(fmaxf(rintf(v.w*inv), -1.f), 1.f);
    g_w4[w][j] = (t0 & 0xFF) | ((t1 & 0xFF) << 8) | ((t2 & 0xFF) << 16) | ((t3 & 0xFF) << 24);
}

// ---------------- activation per-token int8 quant -> packed ----------------
__global__ void actquant_kernel(const float* __restrict__ x) {
    int row = blockIdx.x;                       // 16384 rows, 128 threads
    int t = threadIdx.x;
    float4 v = ((const float4*)(x + (size_t)row * DD))[t];
    float m = fmaxf(fmaxf(fabsf(v.x), fabsf(v.y)), fmaxf(fabsf(v.z), fabsf(v.w)));
    __shared__ float red[128];
    red[t] = m; __syncthreads();
    for (int o = 64; o > 0; o >>= 1) {
        if (t < o) red[t] = fmaxf(red[t], red[t + o]);
        __syncthreads();
    }
    float mx = fmaxf(red[0], EPS_Q);
    float scale = 127.0f / mx;
    int q0 = (int)fminf(fmaxf(rintf(v.x*scale), -128.f), 127.f);
    int q1 = (int)fminf(fmaxf(rintf(v.y*scale), -128.f), 127.f);
    int q2 = (int)fminf(fmaxf(rintf(v.z*scale), -128.f), 127.f);
    int q3 = (int)fminf(fmaxf(rintf(v.w*scale), -128.f), 127.f);
    g_x4[(size_t)row*KW + t] = (q0 & 0xFF) | ((q1 & 0xFF) << 8) | ((q2 & 0xFF) << 16) | ((q3 & 0xFF) << 24);
    if (t == 0) g_xscale[row] = mx / 127.0f;
}

// ================= int8 dp4a GEMM: 128x128 tile, 256 thr, 8x8 micro ==========
// C[i][o] = (sum_k x8[i,k]*w8[o,k]) * xscale[i] * wmean ; K = 128 words
__global__ void qkv_gemm_kernel() {
    __shared__ int As[2][16][128];
    __shared__ int Bs[2][16][128];
    int w = blockIdx.z;
    const int* A = g_x4;
    const int* B = g_w4[w];
    float* C = (w == 0) ? g_q : (w == 1) ? g_k : g_v;
    int row0 = blockIdx.y * 128, col0 = blockIdx.x * 128;
    const int tid = threadIdx.x;
    const int ty8 = (tid >> 4) << 3, tx8 = (tid & 15) << 3;
    int acc[8][8] = {};

    int4 pa[2], pb[2];
    #pragma unroll
    for (int l = 0; l < 2; l++) {
        int idx = tid + l*256, r = idx >> 2, kq = (idx & 3) << 2;
        pa[l] = *(const int4*)(A + (size_t)(row0 + r) * KW + kq);
        pb[l] = *(const int4*)(B + (size_t)(col0 + r) * KW + kq);
    }
    #pragma unroll
    for (int l = 0; l < 2; l++) {
        int idx = tid + l*256, r = idx >> 2, kq = (idx & 3) << 2;
        As[0][kq+0][r] = pa[l].x; As[0][kq+1][r] = pa[l].y; As[0][kq+2][r] = pa[l].z; As[0][kq+3][r] = pa[l].w;
        Bs[0][kq+0][r] = pb[l].x; Bs[0][kq+1][r] = pb[l].y; Bs[0][kq+2][r] = pb[l].z; Bs[0][kq+3][r] = pb[l].w;
    }
    __syncthreads();

    int s = 0;
    for (int k0 = 0; k0 < KW; k0 += 16, s ^= 1) {
        bool nxt = (k0 + 16) < KW;
        if (nxt) {
            #pragma unroll
            for (int l = 0; l < 2; l++) {
                int idx = tid + l*256, r = idx >> 2, kq = (idx & 3) << 2;
                pa[l] = *(const int4*)(A + (size_t)(row0 + r) * KW + k0 + 16 + kq);
                pb[l] = *(const int4*)(B + (size_t)(col0 + r) * KW + k0 + 16 + kq);
            }
        }
        #pragma unroll
        for (int kk = 0; kk < 16; kk++) {
            int4 a0 = *(const int4*)&As[s][kk][ty8];
            int4 a1 = *(const int4*)&As[s][kk][ty8 + 4];
            int4 b0 = *(const int4*)&Bs[s][kk][tx8];
            int4 b1 = *(const int4*)&Bs[s][kk][tx8 + 4];
            int ar[8] = {a0.x, a0.y, a0.z, a0.w, a1.x, a1.y, a1.z, a1.w};
            int br[8] = {b0.x, b0.y, b0.z, b0.w, b1.x, b1.y, b1.z, b1.w};
            #pragma unroll
            for (int r = 0; r < 8; r++)
                #pragma unroll
                for (int c = 0; c < 8; c++)
                    acc[r][c] = __dp4a(ar[r], br[c], acc[r][c]);
        }
        if (nxt) {
            #pragma unroll
            for (int l = 0; l < 2; l++) {
                int idx = tid + l*256, r = idx >> 2, kq = (idx & 3) << 2;
                As[s^1][kq+0][r] = pa[l].x; As[s^1][kq+1][r] = pa[l].y; As[s^1][kq+2][r] = pa[l].z; As[s^1][kq+3][r] = pa[l].w;
                Bs[s^1][kq+0][r] = pb[l].x; Bs[s^1][kq+1][r] = pb[l].y; Bs[s^1][kq+2][r] = pb[l].z; Bs[s^1][kq+3][r] = pb[l].w;
            }
            __syncthreads();
        }
    }
    float wm = g_wmean[w];
    #pragma unroll
    for (int r = 0; r < 8; r++) {
        float sc = g_xscale[row0 + ty8 + r] * wm;
        float* p = C + (size_t)(row0 + ty8 + r) * DD + col0 + tx8;
        *(float4*)(p)     = make_float4(acc[r][0]*sc, acc[r][1]*sc, acc[r][2]*sc, acc[r][3]*sc);
        *(float4*)(p + 4) = make_float4(acc[r][4]*sc, acc[r][5]*sc, acc[r][6]*sc, acc[r][7]*sc);
    }
}

// ================= fp32 NT GEMM, double buffered ==============================
__device__ __forceinline__ void mma_8x8(const float As[16][128], const float Bs[16][128],
                                        int ty8, int tx8, float acc[8][8]) {
    #pragma unroll
    for (int kk = 0; kk < 16; kk++) {
        float4 a0 = *(const float4*)&As[kk][ty8];
        float4 a1 = *(const float4*)&As[kk][ty8 + 4];
        float4 b0 = *(const float4*)&Bs[kk][tx8];
        float4 b1 = *(const float4*)&Bs[kk][tx8 + 4];
        float ar[8] = {a0.x, a0.y, a0.z, a0.w, a1.x, a1.y, a1.z, a1.w};
        float br[8] = {b0.x, b0.y, b0.z, b0.w, b1.x, b1.y, b1.z, b1.w};
        #pragma unroll
        for (int r = 0; r < 8; r++)
            #pragma unroll
            for (int c = 0; c < 8; c++)
                acc[r][c] += ar[r] * br[c];
    }
}

// ---------------- scores = (q @ k^T) * SCALE, causal; skip masked tiles --------
__global__ void scores_kernel() {
    int row0 = blockIdx.y * 128, col0 = blockIdx.x * 128;
    if (col0 > row0 + 127) return;
    __shared__ float As[2][16][128];
    __shared__ float Bs[2][16][128];
    int b = blockIdx.z;
    const float* A = g_q + (size_t)b * SS * DD;
    const float* B = g_k + (size_t)b * SS * DD;
    float* C = g_scores + (size_t)b * SS * SS;
    const int tid = threadIdx.x;
    const int ty8 = (tid >> 4) << 3, tx8 = (tid & 15) << 3;
    float acc[8][8] = {};

    float4 pa[2], pb[2];
    #pragma unroll
    for (int l = 0; l < 2; l++) {
        int idx = tid + l*256, r = idx >> 2, kq = (idx & 3) << 2;
        pa[l] = *(const float4*)(A + (size_t)(row0 + r) * DD + kq);
        pb[l] = *(const float4*)(B + (size_t)(col0 + r) * DD + kq);
    }
    #pragma unroll
    for (int l = 0; l < 2; l++) {
        int idx = tid + l*256, r = idx >> 2, kq = (idx & 3) << 2;
        As[0][kq+0][r] = pa[l].x; As[0][kq+1][r] = pa[l].y; As[0][kq+2][r] = pa[l].z; As[0][kq+3][r] = pa[l].w;
        Bs[0][kq+0][r] = pb[l].x; Bs[0][kq+1][r] = pb[l].y; Bs[0][kq+2][r] = pb[l].z; Bs[0][kq+3][r] = pb[l].w;
    }
    __syncthreads();

    int s = 0;
    for (int k0 = 0; k0 < DD; k0 += 16, s ^= 1) {
        bool nxt = (k0 + 16) < DD;
        if (nxt) {
            #pragma unroll
            for (int l = 0; l < 2; l++) {
                int idx = tid + l*256, r = idx >> 2, kq = (idx & 3) << 2;
                pa[l] = *(const float4*)(A + (size_t)(row0 + r) * DD + k0 + 16 + kq);
                pb[l] = *(const float4*)(B + (size_t)(col0 + r) * DD + k0 + 16 + kq);
            }
        }
        mma_8x8(As[s], Bs[s], ty8, tx8, acc);
        if (nxt) {
            #pragma unroll
            for (int l = 0; l < 2; l++) {
                int idx = tid + l*256, r = idx >> 2, kq = (idx & 3) << 2;
                As[s^1][kq+0][r] = pa[l].x; As[s^1][kq+1][r] = pa[l].y; As[s^1][kq+2][r] = pa[l].z; As[s^1][kq+3][r] = pa[l].w;
                Bs[s^1][kq+0][r] = pb[l].x; Bs[s^1][kq+1][r] = pb[l].y; Bs[s^1][kq+2][r] = pb[l].z; Bs[s^1][kq+3][r] = pb[l].w;
            }
            __syncthreads();
        }
    }
    const float NEG_INF = __int_as_float(0xff800000);
    #pragma unroll
    for (int r = 0; r < 8; r++) {
        int i = row0 + ty8 + r;
        float* p = C + (size_t)i * SS + col0 + tx8;
        #pragma unroll
        for (int c = 0; c < 8; c++) {
            int j = col0 + tx8 + c;
            p[c] = (j <= i) ? acc[r][c] * SCORE_SCALE : NEG_INF;
        }
    }
}

// ---------------- row softmax in smem; prefix only ----------------
__global__ void softmax_kernel() {
    __shared__ float buf[SS];
    __shared__ float red[256];
    size_t row = blockIdx.x;
    int ri = (int)(row & (SS - 1));
    int jend = (ri & ~127) + 128;
    float* p = g_scores + row * SS;
    int t = threadIdx.x;
    float m = __int_as_float(0xff800000);
    for (int j = t; j < jend; j += 256) {
        float v = p[j];
        buf[j] = v;
        m = fmaxf(m, v);
    }
    red[t] = m; __syncthreads();
    for (int o = 128; o > 0; o >>= 1) {
        if (t < o) red[t] = fmaxf(red[t], red[t + o]);
        __syncthreads();
    }
    float mx = red[0];
    __syncthreads();
    float s = 0.f;
    for (int j = t; j < jend; j += 256) {
        float e = expf(buf[j] - mx);
        buf[j] = e;
        s += e;
    }
    red[t] = s; __syncthreads();
    for (int o = 128; o > 0; o >>= 1) {
        if (t < o) red[t] += red[t + o];
        __syncthreads();
    }
    float inv = 1.0f / red[0];
    for (int j = t; j < jend; j += 256) p[j] = buf[j] * inv;
}

// ---------------- out = attn @ v (NN, causal k-range skip), double buffered ----
__global__ void av_kernel(float* __restrict__ out) {
    __shared__ float As[2][16][128];
    __shared__ float Bs[2][16][128];
    int b = blockIdx.z;
    int row0 = blockIdx.y * 128, col0 = blockIdx.x * 128;
    const float* A = g_scores + (size_t)b * SS * SS;
    const float* B = g_v + (size_t)b * SS * DD;
    float* C = out + (size_t)b * SS * DD;
    const int tid = threadIdx.x;
    const int ty8 = (tid >> 4) << 3, tx8 = (tid & 15) << 3;
    float acc[8][8] = {};
    int kend = row0 + 128;

    float4 pa[2], pb[2];
    #pragma unroll
    for (int l = 0; l < 2; l++) {
        int idx = tid + l*256;
        pa[l] = *(const float4*)(A + (size_t)(row0 + (idx >> 2)) * SS + ((idx & 3) << 2));
        pb[l] = *(const float4*)(B + (size_t)(idx >> 5) * DD + col0 + ((idx & 31) << 2));
    }
    #pragma unroll
    for (int l = 0; l < 2; l++) {
        int idx = tid + l*256, r = idx >> 2, kq = (idx & 3) << 2;
        As[0][kq+0][r] = pa[l].x; As[0][kq+1][r] = pa[l].y; As[0][kq+2][r] = pa[l].z; As[0][kq+3][r] = pa[l].w;
        *(float4*)&Bs[0][idx >> 5][(idx & 31) << 2] = pb[l];
    }
    __syncthreads();

    int s = 0;
    for (int k0 = 0; k0 < kend; k0 += 16, s ^= 1) {
        bool nxt = (k0 + 16) < kend;
        if (nxt) {
            #pragma unroll
            for (int l = 0; l < 2; l++) {
                int idx = tid + l*256;
                pa[l] = *(const float4*)(A + (size_t)(row0 + (idx >> 2)) * SS + k0 + 16 + ((idx & 3) << 2));
                pb[l] = *(const float4*)(B + (size_t)(k0 + 16 + (idx >> 5)) * DD + col0 + ((idx & 31) << 2));
            }
        }
        mma_8x8(As[s], Bs[s], ty8, tx8, acc);
        if (nxt) {
            #pragma unroll
            for (int l = 0; l < 2; l++) {
                int idx = tid + l*256, r = idx >> 2, kq = (idx & 3) << 2;
                As[s^1][kq+0][r] = pa[l].x; As[s^1][kq+1][r] = pa[l].y; As[s^1][kq+2][r] = pa[l].z; As[s^1][kq+3][r] = pa[l].w;
                *(float4*)&Bs[s^1][idx >> 5][(idx & 31) << 2] = pb[l];
            }
            __syncthreads();
        }
    }
    #pragma unroll
    for (int r = 0; r < 8; r++) {
        float* p = C + (size_t)(row0 + ty8 + r) * DD + col0 + tx8;
        *(float4*)(p)     = make_float4(acc[r][0], acc[r][1], acc[r][2], acc[r][3]);
        *(float4*)(p + 4) = make_float4(acc[r][4], acc[r][5], acc[r][6], acc[r][7]);
    }
}

// ---------------- launch ----------------
extern "C" void kernel_launch(void* const* d_in, const int* in_sizes, int n_in,
                              void* d_out, int out_size) {
    (void)in_sizes; (void)n_in; (void)out_size;
    const float* x  = (const float*)d_in[0];
    const float* Wq = (const float*)d_in[1];
    const float* Wk = (const float*)d_in[2];
    const float* Wv = (const float*)d_in[3];
    float* out = (float*)d_out;

    wmean_kernel<<<3, 256>>>(Wq, Wk, Wv);
    wquant_kernel<<<(3*DD*KW + 255)/256, 256>>>(Wq, Wk, Wv);
    actquant_kernel<<<MM, 128>>>(x);

    dim3 gqkv(DD/128, MM/128, 3);          // (4, 128, 3)
    qkv_gemm_kernel<<<gqkv, 256>>>();

    dim3 gsc(SS/128, SS/128, BB);          // (16, 16, 8)
    scores_kernel<<<gsc, 256>>>();

    softmax_kernel<<<MM, 256>>>();

    dim3 gav(DD/128, SS/128, BB);          // (4, 16, 8)
    av_kernel<<<gav, 256>>>(out);
}

// round 10
// speedup vs baseline: 2.6876x; 1.7274x over previous
#include <cuda_runtime.h>
#include <cuda_bf16.h>
#include <math.h>
#include <stdint.h>

// Problem constants: B=8, S=2048, D=512
#define BB 8
#define SS 2048
#define DD 512
#define MM (BB*SS)
#define KW (DD/4)
#define EPS_Q 1e-5f
#define SCORE_SCALE 0.35355339059327373f   // 8^-0.5

// ---------------- scratch ----------------
__device__ float g_wmean[3];
__device__ int   g_w4[3][DD*KW];
__device__ int   g_x4[MM*KW];
__device__ float g_xscale[MM];
__device__ __nv_bfloat16 g_qhi[MM*DD];
__device__ __nv_bfloat16 g_qlo[MM*DD];
__device__ __nv_bfloat16 g_khi[MM*DD];
__device__ __nv_bfloat16 g_klo[MM*DD];
__device__ float g_v[MM*DD];
__device__ __nv_bfloat16 g_vthi[(size_t)BB*DD*SS];   // [b][d][j]
__device__ __nv_bfloat16 g_vtlo[(size_t)BB*DD*SS];
__device__ float g_scores[(size_t)BB*SS*SS];          // fp32 logits
__device__ __nv_bfloat16 g_ahi[(size_t)BB*SS*SS];     // attn weights hi/lo
__device__ __nv_bfloat16 g_alo[(size_t)BB*SS*SS];

// ---------------- weight mean(|w|) ----------------
__global__ void wmean_kernel(const float* __restrict__ Wq,
                             const float* __restrict__ Wk,
                             const float* __restrict__ Wv) {
    const float* W = (blockIdx.x == 0) ? Wq : (blockIdx.x == 1) ? Wk : Wv;
    __shared__ float red[256];
    float s = 0.f;
    for (int i = threadIdx.x; i < DD*DD; i += 256) s += fabsf(W[i]);
    red[threadIdx.x] = s;
    __syncthreads();
    for (int o = 128; o > 0; o >>= 1) {
        if (threadIdx.x < o) red[threadIdx.x] += red[threadIdx.x + o];
        __syncthreads();
    }
    if (threadIdx.x == 0)
        g_wmean[blockIdx.x] = fmaxf(red[0] / (float)(DD*DD), EPS_Q);
}

// ---------------- weight ternary quant -> packed int8 ----------------
__global__ void wquant_kernel(const float* __restrict__ Wq,
                              const float* __restrict__ Wk,
                              const float* __restrict__ Wv) {
    int i = blockIdx.x * blockDim.x + threadIdx.x;
    if (i >= 3*DD*KW) return;
    int w = i / (DD*KW), j = i - w*(DD*KW);
    const float* W = (w == 0) ? Wq : (w == 1) ? Wk : Wv;
    float inv = 1.0f / g_wmean[w];
    float4 v = *(const float4*)(W + j*4);
    int t0 = (int)fminf(fmaxf(rintf(v.x*inv), -1.f), 1.f);
    int t1 = (int)fminf(fmaxf(rintf(v.y*inv), -1.f), 1.f);
    int t2 = (int)fminf(fmaxf(rintf(v.z*inv), -1.f), 1.f);
    int t3 = (int)fminf(fmaxf(rintf(v.w*inv), -1.f), 1.f);
    g_w4[w][j] = (t0 & 0xFF) | ((t1 & 0xFF) << 8) | ((t2 & 0xFF) << 16) | ((t3 & 0xFF) << 24);
}

// ---------------- activation per-token int8 quant -> packed ----------------
__global__ void actquant_kernel(const float* __restrict__ x) {
    int row = blockIdx.x;
    int t = threadIdx.x;
    float4 v = ((const float4*)(x + (size_t)row * DD))[t];
    float m = fmaxf(fmaxf(fabsf(v.x), fabsf(v.y)), fmaxf(fabsf(v.z), fabsf(v.w)));
    __shared__ float red[128];
    red[t] = m; __syncthreads();
    for (int o = 64; o > 0; o >>= 1) {
        if (t < o) red[t] = fmaxf(red[t], red[t + o]);
        __syncthreads();
    }
    float mx = fmaxf(red[0], EPS_Q);
    float scale = 127.0f / mx;
    int q0 = (int)fminf(fmaxf(rintf(v.x*scale), -128.f), 127.f);
    int q1 = (int)fminf(fmaxf(rintf(v.y*scale), -128.f), 127.f);
    int q2 = (int)fminf(fmaxf(rintf(v.z*scale), -128.f), 127.f);
    int q3 = (int)fminf(fmaxf(rintf(v.w*scale), -128.f), 127.f);
    g_x4[(size_t)row*KW + t] = (q0 & 0xFF) | ((q1 & 0xFF) << 8) | ((q2 & 0xFF) << 16) | ((q3 & 0xFF) << 24);
    if (t == 0) g_xscale[row] = mx / 127.0f;
}

// ================= int8 dp4a QKV GEMM (epilogue: bf16 hi/lo for q,k; fp32 v) ==
__global__ void qkv_gemm_kernel() {
    __shared__ int As[2][16][128];
    __shared__ int Bs[2][16][128];
    int w = blockIdx.z;
    const int* A = g_x4;
    const int* B = g_w4[w];
    int row0 = blockIdx.y * 128, col0 = blockIdx.x * 128;
    const int tid = threadIdx.x;
    const int ty8 = (tid >> 4) << 3, tx8 = (tid & 15) << 3;
    int acc[8][8] = {};

    int4 pa[2], pb[2];
    #pragma unroll
    for (int l = 0; l < 2; l++) {
        int idx = tid + l*256, r = idx >> 2, kq = (idx & 3) << 2;
        pa[l] = *(const int4*)(A + (size_t)(row0 + r) * KW + kq);
        pb[l] = *(const int4*)(B + (size_t)(col0 + r) * KW + kq);
    }
    #pragma unroll
    for (int l = 0; l < 2; l++) {
        int idx = tid + l*256, r = idx >> 2, kq = (idx & 3) << 2;
        As[0][kq+0][r] = pa[l].x; As[0][kq+1][r] = pa[l].y; As[0][kq+2][r] = pa[l].z; As[0][kq+3][r] = pa[l].w;
        Bs[0][kq+0][r] = pb[l].x; Bs[0][kq+1][r] = pb[l].y; Bs[0][kq+2][r] = pb[l].z; Bs[0][kq+3][r] = pb[l].w;
    }
    __syncthreads();

    int s = 0;
    for (int k0 = 0; k0 < KW; k0 += 16, s ^= 1) {
        bool nxt = (k0 + 16) < KW;
        if (nxt) {
            #pragma unroll
            for (int l = 0; l < 2; l++) {
                int idx = tid + l*256, r = idx >> 2, kq = (idx & 3) << 2;
                pa[l] = *(const int4*)(A + (size_t)(row0 + r) * KW + k0 + 16 + kq);
                pb[l] = *(const int4*)(B + (size_t)(col0 + r) * KW + k0 + 16 + kq);
            }
        }
        #pragma unroll
        for (int kk = 0; kk < 16; kk++) {
            int4 a0 = *(const int4*)&As[s][kk][ty8];
            int4 a1 = *(const int4*)&As[s][kk][ty8 + 4];
            int4 b0 = *(const int4*)&Bs[s][kk][tx8];
            int4 b1 = *(const int4*)&Bs[s][kk][tx8 + 4];
            int ar[8] = {a0.x, a0.y, a0.z, a0.w, a1.x, a1.y, a1.z, a1.w};
            int br[8] = {b0.x, b0.y, b0.z, b0.w, b1.x, b1.y, b1.z, b1.w};
            #pragma unroll
            for (int r = 0; r < 8; r++)
                #pragma unroll
                for (int c = 0; c < 8; c++)
                    acc[r][c] = __dp4a(ar[r], br[c], acc[r][c]);
        }
        if (nxt) {
            #pragma unroll
            for (int l = 0; l < 2; l++) {
                int idx = tid + l*256, r = idx >> 2, kq = (idx & 3) << 2;
                As[s^1][kq+0][r] = pa[l].x; As[s^1][kq+1][r] = pa[l].y; As[s^1][kq+2][r] = pa[l].z; As[s^1][kq+3][r] = pa[l].w;
                Bs[s^1][kq+0][r] = pb[l].x; Bs[s^1][kq+1][r] = pb[l].y; Bs[s^1][kq+2][r] = pb[l].z; Bs[s^1][kq+3][r] = pb[l].w;
            }
            __syncthreads();
        }
    }
    float wm = g_wmean[w];
    if (w == 2) {
        #pragma unroll
        for (int r = 0; r < 8; r++) {
            float sc = g_xscale[row0 + ty8 + r] * wm;
            float* p = g_v + (size_t)(row0 + ty8 + r) * DD + col0 + tx8;
            *(float4*)(p)     = make_float4(acc[r][0]*sc, acc[r][1]*sc, acc[r][2]*sc, acc[r][3]*sc);
            *(float4*)(p + 4) = make_float4(acc[r][4]*sc, acc[r][5]*sc, acc[r][6]*sc, acc[r][7]*sc);
        }
    } else {
        __nv_bfloat16* ph = (w == 0) ? g_qhi : g_khi;
        __nv_bfloat16* pl = (w == 0) ? g_qlo : g_klo;
        #pragma unroll
        for (int r = 0; r < 8; r++) {
            float sc = g_xscale[row0 + ty8 + r] * wm;
            __align__(16) __nv_bfloat16 h[8], lo[8];
            #pragma unroll
            for (int c = 0; c < 8; c++) {
                float v = acc[r][c] * sc;
                h[c] = __float2bfloat16(v);
                lo[c] = __float2bfloat16(v - __bfloat162float(h[c]));
            }
            size_t o = (size_t)(row0 + ty8 + r) * DD + col0 + tx8;
            *(uint4*)(ph + o) = *(const uint4*)h;
            *(uint4*)(pl + o) = *(const uint4*)lo;
        }
    }
}

// ---------------- transpose v -> vt hi/lo bf16 ----------------
__global__ void vtrans_kernel() {
    __shared__ float t[32][33];
    int b = blockIdx.z, d0 = blockIdx.x*32, j0 = blockIdx.y*32;
    int tx = threadIdx.x, ty = threadIdx.y;    // 32 x 8
    #pragma unroll
    for (int l = 0; l < 4; l++) {
        int j = ty + l*8;
        t[j][tx] = g_v[((size_t)b*SS + j0 + j) * DD + d0 + tx];
    }
    __syncthreads();
    #pragma unroll
    for (int l = 0; l < 4; l++) {
        int d = ty + l*8;
        float v = t[tx][d];
        __nv_bfloat16 h = __float2bfloat16(v);
        size_t o = ((size_t)b*DD + d0 + d) * SS + j0 + tx;
        g_vthi[o] = h;
        g_vtlo[o] = __float2bfloat16(v - __bfloat162float(h));
    }
}

// ================= split-bf16 mma.sync GEMM machinery =========================
// CTA tile 128x128, 8 warps (2x4), warp tile 64x32 (4x4 atoms m16n8k16).
// Smem per stage: 4 tiles of 128x32 bf16, row stride 40 (conflict-free frags).

#define TILE_ELEMS (128*40)            // 5120 bf16
#define STAGE_ELEMS (4*TILE_ELEMS)     // 20480
#define SMEM_MMA_BYTES (2*STAGE_ELEMS*2)  // 81920

__device__ __forceinline__ void mma16816(float* c, const uint32_t* a, const uint32_t* b) {
    asm volatile("mma.sync.aligned.m16n8k16.row.col.f32.bf16.bf16.f32 "
        "{%0,%1,%2,%3}, {%4,%5,%6,%7}, {%8,%9}, {%0,%1,%2,%3};"
        : "+f"(c[0]), "+f"(c[1]), "+f"(c[2]), "+f"(c[3])
        : "r"(a[0]), "r"(a[1]), "r"(a[2]), "r"(a[3]), "r"(b[0]), "r"(b[1]));
}

// acc layout: acc[matom][natom][4]
__device__ __forceinline__ void gemm_split(
    const __nv_bfloat16* __restrict__ Ahi, const __nv_bfloat16* __restrict__ Alo,
    size_t rA, int strdA,
    const __nv_bfloat16* __restrict__ Bhi, const __nv_bfloat16* __restrict__ Blo,
    size_t rB, int strdB,
    int nch, __nv_bfloat16* sm, float acc[4][4][4])
{
    const int tid = threadIdx.x;
    const int lane = tid & 31, gid = lane >> 2, tg = lane & 3;
    const int wid = tid >> 5;
    const int wm = (wid >> 2) * 64, wn = (wid & 3) * 32;
    const int lr = tid >> 2, lc = (tid & 3) * 8;   // loader: row, col-group

    uint4 pr[8];
    // prologue: chunk 0
    #pragma unroll
    for (int l = 0; l < 2; l++) {
        int r = lr + l*64;
        size_t oa = (rA + r) * (size_t)strdA + lc;
        size_t ob = (rB + r) * (size_t)strdB + lc;
        pr[l*4+0] = *(const uint4*)(Ahi + oa);
        pr[l*4+1] = *(const uint4*)(Alo + oa);
        pr[l*4+2] = *(const uint4*)(Bhi + ob);
        pr[l*4+3] = *(const uint4*)(Blo + ob);
    }
    #pragma unroll
    for (int l = 0; l < 2; l++) {
        int r = lr + l*64;
        __nv_bfloat16* base = sm + r*40 + lc;
        *(uint4*)(base)                = pr[l*4+0];
        *(uint4*)(base + TILE_ELEMS)   = pr[l*4+1];
        *(uint4*)(base + 2*TILE_ELEMS) = pr[l*4+2];
        *(uint4*)(base + 3*TILE_ELEMS) = pr[l*4+3];
    }
    __syncthreads();

    for (int ch = 0; ch < nch; ch++) {
        int s = ch & 1;
        bool nxt = (ch + 1) < nch;
        if (nxt) {
            int k0 = (ch + 1) * 32;
            #pragma unroll
            for (int l = 0; l < 2; l++) {
                int r = lr + l*64;
                size_t oa = (rA + r) * (size_t)strdA + k0 + lc;
                size_t ob = (rB + r) * (size_t)strdB + k0 + lc;
                pr[l*4+0] = *(const uint4*)(Ahi + oa);
                pr[l*4+1] = *(const uint4*)(Alo + oa);
                pr[l*4+2] = *(const uint4*)(Bhi + ob);
                pr[l*4+3] = *(const uint4*)(Blo + ob);
            }
        }
        // compute stage s
        {
            const __nv_bfloat16* sAhi = sm + s*STAGE_ELEMS;
            const __nv_bfloat16* sAlo = sAhi + TILE_ELEMS;
            const __nv_bfloat16* sBhi = sAhi + 2*TILE_ELEMS;
            const __nv_bfloat16* sBlo = sAhi + 3*TILE_ELEMS;
            #pragma unroll
            for (int ks = 0; ks < 2; ks++) {
                int kof = ks*16 + tg*2;
                uint32_t af[4][4], bh[4][2], bl[4][2];
                #pragma unroll
                for (int m = 0; m < 4; m++) {
                    const __nv_bfloat16* p = sAhi + (wm + m*16 + gid)*40 + kof;
                    af[m][0] = *(const uint32_t*)p;
                    af[m][1] = *(const uint32_t*)(p + 320);
                    af[m][2] = *(const uint32_t*)(p + 8);
                    af[m][3] = *(const uint32_t*)(p + 328);
                }
                #pragma unroll
                for (int n = 0; n < 4; n++) {
                    const __nv_bfloat16* p = sBhi + (wn + n*8 + gid)*40 + kof;
                    bh[n][0] = *(const uint32_t*)p;
                    bh[n][1] = *(const uint32_t*)(p + 8);
                    const __nv_bfloat16* q = sBlo + (wn + n*8 + gid)*40 + kof;
                    bl[n][0] = *(const uint32_t*)q;
                    bl[n][1] = *(const uint32_t*)(q + 8);
                }
                #pragma unroll
                for (int m = 0; m < 4; m++)
                    #pragma unroll
                    for (int n = 0; n < 4; n++)
                        mma16816(acc[m][n], af[m], bh[n]);   // hi*hi
                #pragma unroll
                for (int m = 0; m < 4; m++)
                    #pragma unroll
                    for (int n = 0; n < 4; n++)
                        mma16816(acc[m][n], af[m], bl[n]);   // hi*lo
                #pragma unroll
                for (int m = 0; m < 4; m++) {
                    const __nv_bfloat16* p = sAlo + (wm + m*16 + gid)*40 + kof;
                    af[m][0] = *(const uint32_t*)p;
                    af[m][1] = *(const uint32_t*)(p + 320);
                    af[m][2] = *(const uint32_t*)(p + 8);
                    af[m][3] = *(const uint32_t*)(p + 328);
                }
                #pragma unroll
                for (int m = 0; m < 4; m++)
                    #pragma unroll
                    for (int n = 0; n < 4; n++)
                        mma16816(acc[m][n], af[m], bh[n]);   // lo*hi
            }
        }
        if (nxt) {
            int so = (s ^ 1) * STAGE_ELEMS;
            #pragma unroll
            for (int l = 0; l < 2; l++) {
                int r = lr + l*64;
                __nv_bfloat16* base = sm + so + r*40 + lc;
                *(uint4*)(base)                = pr[l*4+0];
                *(uint4*)(base + TILE_ELEMS)   = pr[l*4+1];
                *(uint4*)(base + 2*TILE_ELEMS) = pr[l*4+2];
                *(uint4*)(base + 3*TILE_ELEMS) = pr[l*4+3];
            }
        }
        __syncthreads();
    }
}

// ================ scores = (q@k^T)*SCALE with causal mask (mma.sync) ==========
__global__ void __launch_bounds__(256) scores_mma_kernel() {
    int row0 = blockIdx.y * 128, col0 = blockIdx.x * 128;
    if (col0 > row0) return;
    int b = blockIdx.z;
    extern __shared__ __nv_bfloat16 sm[];
    float acc[4][4][4] = {};
    gemm_split(g_qhi, g_qlo, (size_t)b*SS + row0, DD,
               g_khi, g_klo, (size_t)b*SS + col0, DD,
               DD/32, sm, acc);

    const int tid = threadIdx.x;
    const int lane = tid & 31, gid = lane >> 2, tg = lane & 3;
    const int wid = tid >> 5;
    const int wm = (wid >> 2) * 64, wn = (wid & 3) * 32;
    const float NEG_INF = __int_as_float(0xff800000);
    bool diag = (col0 == row0);
    #pragma unroll
    for (int m = 0; m < 4; m++) {
        #pragma unroll
        for (int h = 0; h < 2; h++) {
            int i = row0 + wm + m*16 + gid + h*8;
            float* prow = g_scores + ((size_t)b*SS + i) * SS;
            #pragma unroll
            for (int n = 0; n < 4; n++) {
                int j = col0 + wn + n*8 + tg*2;
                float2 v;
                v.x = acc[m][n][h*2+0] * SCORE_SCALE;
                v.y = acc[m][n][h*2+1] * SCORE_SCALE;
                if (diag) {
                    if (j > i)   v.x = NEG_INF;
                    if (j+1 > i) v.y = NEG_INF;
                }
                *(float2*)(prow + j) = v;
            }
        }
    }
}

// ---------------- row softmax (smem) -> attn hi/lo bf16 ----------------
__global__ void softmax_kernel() {
    __shared__ float buf[SS];
    __shared__ float red[256];
    size_t row = blockIdx.x;
    int ri = (int)(row & (SS - 1));
    int jend = (ri & ~127) + 128;
    const float* p = g_scores + row * SS;
    __nv_bfloat16* ph = g_ahi + row * SS;
    __nv_bfloat16* pl = g_alo + row * SS;
    int t = threadIdx.x;
    float m = __int_as_float(0xff800000);
    for (int j = t; j < jend; j += 256) {
        float v = p[j];
        buf[j] = v;
        m = fmaxf(m, v);
    }
    red[t] = m; __syncthreads();
    for (int o = 128; o > 0; o >>= 1) {
        if (t < o) red[t] = fmaxf(red[t], red[t + o]);
        __syncthreads();
    }
    float mx = red[0];
    __syncthreads();
    float s = 0.f;
    for (int j = t; j < jend; j += 256) {
        float e = expf(buf[j] - mx);
        buf[j] = e;
        s += e;
    }
    red[t] = s; __syncthreads();
    for (int o = 128; o > 0; o >>= 1) {
        if (t < o) red[t] += red[t + o];
        __syncthreads();
    }
    float inv = 1.0f / red[0];
    for (int j = t; j < jend; j += 256) {
        float v = buf[j] * inv;
        __nv_bfloat16 h = __float2bfloat16(v);
        ph[j] = h;
        pl[j] = __float2bfloat16(v - __bfloat162float(h));
    }
}

// ================ out = attn @ v (NT vs vt, mma.sync) =========================
__global__ void __launch_bounds__(256) av_mma_kernel(float* __restrict__ out) {
    int col0 = blockIdx.x * 128;
    int row0 = blockIdx.y * 128;
    int b = blockIdx.z;
    extern __shared__ __nv_bfloat16 sm[];
    float acc[4][4][4] = {};
    int nch = (row0 >> 5) + 4;                     // causal prefix: (row0+128)/32 chunks
    gemm_split(g_ahi, g_alo, (size_t)b*SS + row0, SS,
               g_vthi, g_vtlo, (size_t)b*DD + col0, SS,
               nch, sm, acc);

    const int tid = threadIdx.x;
    const int lane = tid & 31, gid = lane >> 2, tg = lane & 3;
    const int wid = tid >> 5;
    const int wm = (wid >> 2) * 64, wn = (wid & 3) * 32;
    #pragma unroll
    for (int m = 0; m < 4; m++) {
        #pragma unroll
        for (int h = 0; h < 2; h++) {
            int i = row0 + wm + m*16 + gid + h*8;
            float* prow = out + ((size_t)b*SS + i) * DD;
            #pragma unroll
            for (int n = 0; n < 4; n++) {
                int j = col0 + wn + n*8 + tg*2;
                float2 v;
                v.x = acc[m][n][h*2+0];
                v.y = acc[m][n][h*2+1];
                *(float2*)(prow + j) = v;
            }
        }
    }
}

// ---------------- launch ----------------
extern "C" void kernel_launch(void* const* d_in, const int* in_sizes, int n_in,
                              void* d_out, int out_size) {
    (void)in_sizes; (void)n_in; (void)out_size;
    const float* x  = (const float*)d_in[0];
    const float* Wq = (const float*)d_in[1];
    const float* Wk = (const float*)d_in[2];
    const float* Wv = (const float*)d_in[3];
    float* out = (float*)d_out;

    static int smem_set = 0;
    if (!smem_set) {
        cudaFuncSetAttribute(scores_mma_kernel, cudaFuncAttributeMaxDynamicSharedMemorySize, SMEM_MMA_BYTES);
        cudaFuncSetAttribute(av_mma_kernel,     cudaFuncAttributeMaxDynamicSharedMemorySize, SMEM_MMA_BYTES);
        smem_set = 1;
    }

    wmean_kernel<<<3, 256>>>(Wq, Wk, Wv);
    wquant_kernel<<<(3*DD*KW + 255)/256, 256>>>(Wq, Wk, Wv);
    actquant_kernel<<<MM, 128>>>(x);

    dim3 gqkv(DD/128, MM/128, 3);
    qkv_gemm_kernel<<<gqkv, 256>>>();

    dim3 gvt(DD/32, SS/32, BB);
    vtrans_kernel<<<gvt, dim3(32, 8)>>>();

    dim3 gsc(SS/128, SS/128, BB);
    scores_mma_kernel<<<gsc, 256, SMEM_MMA_BYTES>>>();

    softmax_kernel<<<MM, 256>>>();

    dim3 gav(DD/128, SS/128, BB);
    av_mma_kernel<<<gav, 256, SMEM_MMA_BYTES>>>(out);
}

// round 12
// speedup vs baseline: 2.7388x; 1.0191x over previous
#include <cuda_runtime.h>
#include <cuda_bf16.h>
#include <math.h>
#include <stdint.h>

// Problem constants: B=8, S=2048, D=512
#define BB 8
#define SS 2048
#define DD 512
#define MM (BB*SS)
#define KW (DD/4)
#define EPS_Q 1e-5f
#define SCORE_SCALE 0.35355339059327373f   // 8^-0.5

// ---------------- scratch ----------------
__device__ float g_wmean[3];
__device__ int   g_w4[3][DD*KW];
__device__ int   g_x4[MM*KW];
__device__ float g_xscale[MM];
__device__ __nv_bfloat16 g_qhi[MM*DD];
__device__ __nv_bfloat16 g_qlo[MM*DD];
__device__ __nv_bfloat16 g_khi[MM*DD];
__device__ __nv_bfloat16 g_klo[MM*DD];
__device__ float g_v[MM*DD];
__device__ __nv_bfloat16 g_vthi[(size_t)BB*DD*SS];   // [b][d][j]
__device__ __nv_bfloat16 g_vtlo[(size_t)BB*DD*SS];
__device__ float g_scores[(size_t)BB*SS*SS];          // fp32 logits
__device__ __nv_bfloat16 g_ahi[(size_t)BB*SS*SS];     // attn weights hi/lo
__device__ __nv_bfloat16 g_alo[(size_t)BB*SS*SS];

// ---------------- weight mean(|w|) ----------------
__global__ void wmean_kernel(const float* __restrict__ Wq,
                             const float* __restrict__ Wk,
                             const float* __restrict__ Wv) {
    const float* W = (blockIdx.x == 0) ? Wq : (blockIdx.x == 1) ? Wk : Wv;
    __shared__ float red[256];
    float s = 0.f;
    for (int i = threadIdx.x; i < DD*DD; i += 256) s += fabsf(W[i]);
    red[threadIdx.x] = s;
    __syncthreads();
    for (int o = 128; o > 0; o >>= 1) {
        if (threadIdx.x < o) red[threadIdx.x] += red[threadIdx.x + o];
        __syncthreads();
    }
    if (threadIdx.x == 0)
        g_wmean[blockIdx.x] = fmaxf(red[0] / (float)(DD*DD), EPS_Q);
}

// ---------------- weight ternary quant -> packed int8 ----------------
__global__ void wquant_kernel(const float* __restrict__ Wq,
                              const float* __restrict__ Wk,
                              const float* __restrict__ Wv) {
    int i = blockIdx.x * blockDim.x + threadIdx.x;
    if (i >= 3*DD*KW) return;
    int w = i / (DD*KW), j = i - w*(DD*KW);
    const float* W = (w == 0) ? Wq : (w == 1) ? Wk : Wv;
    float inv = 1.0f / g_wmean[w];
    float4 v = *(const float4*)(W + j*4);
    int t0 = (int)fminf(fmaxf(rintf(v.x*inv), -1.f), 1.f);
    int t1 = (int)fminf(fmaxf(rintf(v.y*inv), -1.f), 1.f);
    int t2 = (int)fminf(fmaxf(rintf(v.z*inv), -1.f), 1.f);
    int t3 = (int)fminf(fmaxf(rintf(v.w*inv), -1.f), 1.f);
    g_w4[w][j] = (t0 & 0xFF) | ((t1 & 0xFF) << 8) | ((t2 & 0xFF) << 16) | ((t3 & 0xFF) << 24);
}

// ---------------- activation per-token int8 quant -> packed ----------------
__global__ void actquant_kernel(const float* __restrict__ x) {
    int row = blockIdx.x;
    int t = threadIdx.x;
    float4 v = ((const float4*)(x + (size_t)row * DD))[t];
    float m = fmaxf(fmaxf(fabsf(v.x), fabsf(v.y)), fmaxf(fabsf(v.z), fabsf(v.w)));
    __shared__ float red[128];
    red[t] = m; __syncthreads();
    for (int o = 64; o > 0; o >>= 1) {
        if (t < o) red[t] = fmaxf(red[t], red[t + o]);
        __syncthreads();
    }
    float mx = fmaxf(red[0], EPS_Q);
    float scale = 127.0f / mx;
    int q0 = (int)fminf(fmaxf(rintf(v.x*scale), -128.f), 127.f);
    int q1 = (int)fminf(fmaxf(rintf(v.y*scale), -128.f), 127.f);
    int q2 = (int)fminf(fmaxf(rintf(v.z*scale), -128.f), 127.f);
    int q3 = (int)fminf(fmaxf(rintf(v.w*scale), -128.f), 127.f);
    g_x4[(size_t)row*KW + t] = (q0 & 0xFF) | ((q1 & 0xFF) << 8) | ((q2 & 0xFF) << 16) | ((q3 & 0xFF) << 24);
    if (t == 0) g_xscale[row] = mx / 127.0f;
}

// ================= int8 tensor-core QKV GEMM ==================================
// mma.sync m16n8k32 s8 — exact (int32 accumulate). CTA 128x128, 8 warps (2x4),
// warp 64x32. K chunk = 16 words (64 int8), double-buffered, smem stride 20 words.

__device__ __forceinline__ void imma16832(int* c, const uint32_t* a, const uint32_t* b) {
    asm volatile("mma.sync.aligned.m16n8k32.row.col.s32.s8.s8.s32 "
        "{%0,%1,%2,%3}, {%4,%5,%6,%7}, {%8,%9}, {%0,%1,%2,%3};"
        : "+r"(c[0]), "+r"(c[1]), "+r"(c[2]), "+r"(c[3])
        : "r"(a[0]), "r"(a[1]), "r"(a[2]), "r"(a[3]), "r"(b[0]), "r"(b[1]));
}

#define QT_STRIDE 20               // words per row (80B, conflict-free frag loads)
#define QT_WORDS  (128*QT_STRIDE)

__global__ void __launch_bounds__(256) qkv_imma_kernel() {
    __shared__ uint32_t sA[2][QT_WORDS];
    __shared__ uint32_t sB[2][QT_WORDS];
    int w = blockIdx.z;
    const uint32_t* A = (const uint32_t*)g_x4;
    const uint32_t* B = (const uint32_t*)g_w4[w];
    int row0 = blockIdx.y * 128, col0 = blockIdx.x * 128;
    const int tid = threadIdx.x;
    const int lane = tid & 31, gid = lane >> 2, tg = lane & 3;
    const int wid = tid >> 5;
    const int wm = (wid >> 2) * 64, wn = (wid & 3) * 32;
    int acc[4][4][4] = {};

    uint4 pa[2], pb[2];
    // prologue: chunk 0
    #pragma unroll
    for (int l = 0; l < 2; l++) {
        int slot = tid + l*256, r = slot >> 2, c = slot & 3;
        pa[l] = *(const uint4*)(A + (size_t)(row0 + r) * KW + c*4);
        pb[l] = *(const uint4*)(B + (size_t)(col0 + r) * KW + c*4);
    }
    #pragma unroll
    for (int l = 0; l < 2; l++) {
        int slot = tid + l*256, r = slot >> 2, c = slot & 3;
        *(uint4*)&sA[0][r*QT_STRIDE + c*4] = pa[l];
        *(uint4*)&sB[0][r*QT_STRIDE + c*4] = pb[l];
    }
    __syncthreads();

    for (int ch = 0; ch < 8; ch++) {
        int s = ch & 1;
        bool nxt = (ch + 1) < 8;
        if (nxt) {
            int k0 = (ch + 1) * 16;
            #pragma unroll
            for (int l = 0; l < 2; l++) {
                int slot = tid + l*256, r = slot >> 2, c = slot & 3;
                pa[l] = *(const uint4*)(A + (size_t)(row0 + r) * KW + k0 + c*4);
                pb[l] = *(const uint4*)(B + (size_t)(col0 + r) * KW + k0 + c*4);
            }
        }
        #pragma unroll
        for (int ks = 0; ks < 2; ks++) {
            int kof = ks*8 + tg;
            uint32_t af[4][4], bf[4][2];
            #pragma unroll
            for (int m = 0; m < 4; m++) {
                const uint32_t* p = &sA[s][(wm + m*16 + gid)*QT_STRIDE + kof];
                af[m][0] = p[0];
                af[m][1] = p[8*QT_STRIDE];
                af[m][2] = p[4];
                af[m][3] = p[8*QT_STRIDE + 4];
            }
            #pragma unroll
            for (int n = 0; n < 4; n++) {
                const uint32_t* p = &sB[s][(wn + n*8 + gid)*QT_STRIDE + kof];
                bf[n][0] = p[0];
                bf[n][1] = p[4];
            }
            #pragma unroll
            for (int m = 0; m < 4; m++)
                #pragma unroll
                for (int n = 0; n < 4; n++)
                    imma16832(acc[m][n], af[m], bf[n]);
        }
        if (nxt) {
            #pragma unroll
            for (int l = 0; l < 2; l++) {
                int slot = tid + l*256, r = slot >> 2, c = slot & 3;
                *(uint4*)&sA[s^1][r*QT_STRIDE + c*4] = pa[l];
                *(uint4*)&sB[s^1][r*QT_STRIDE + c*4] = pb[l];
            }
        }
        __syncthreads();
    }

    float wmv = g_wmean[w];
    #pragma unroll
    for (int m = 0; m < 4; m++) {
        #pragma unroll
        for (int h = 0; h < 2; h++) {
            int i = row0 + wm + m*16 + gid + h*8;
            float sc = g_xscale[i] * wmv;
            if (w == 2) {
                float* prow = g_v + (size_t)i * DD;
                #pragma unroll
                for (int n = 0; n < 4; n++) {
                    int j = col0 + wn + n*8 + tg*2;
                    float2 v;
                    v.x = (float)acc[m][n][h*2+0] * sc;
                    v.y = (float)acc[m][n][h*2+1] * sc;
                    *(float2*)(prow + j) = v;
                }
            } else {
                __nv_bfloat16* ph = ((w == 0) ? g_qhi : g_khi) + (size_t)i * DD;
                __nv_bfloat16* pl = ((w == 0) ? g_qlo : g_klo) + (size_t)i * DD;
                #pragma unroll
                for (int n = 0; n < 4; n++) {
                    int j = col0 + wn + n*8 + tg*2;
                    float v0 = (float)acc[m][n][h*2+0] * sc;
                    float v1 = (float)acc[m][n][h*2+1] * sc;
                    __nv_bfloat16 h0 = __float2bfloat16(v0);
                    __nv_bfloat16 h1 = __float2bfloat16(v1);
                    __nv_bfloat162 hh; hh.x = h0; hh.y = h1;
                    __nv_bfloat162 ll;
                    ll.x = __float2bfloat16(v0 - __bfloat162float(h0));
                    ll.y = __float2bfloat16(v1 - __bfloat162float(h1));
                    *(__nv_bfloat162*)(ph + j) = hh;
                    *(__nv_bfloat162*)(pl + j) = ll;
                }
            }
        }
    }
}

// ---------------- transpose v -> vt hi/lo bf16 ----------------
__global__ void vtrans_kernel() {
    __shared__ float t[32][33];
    int b = blockIdx.z, d0 = blockIdx.x*32, j0 = blockIdx.y*32;
    int tx = threadIdx.x, ty = threadIdx.y;    // 32 x 8
    #pragma unroll
    for (int l = 0; l < 4; l++) {
        int j = ty + l*8;
        t[j][tx] = g_v[((size_t)b*SS + j0 + j) * DD + d0 + tx];
    }
    __syncthreads();
    #pragma unroll
    for (int l = 0; l < 4; l++) {
        int d = ty + l*8;
        float v = t[tx][d];
        __nv_bfloat16 h = __float2bfloat16(v);
        size_t o = ((size_t)b*DD + d0 + d) * SS + j0 + tx;
        g_vthi[o] = h;
        g_vtlo[o] = __float2bfloat16(v - __bfloat162float(h));
    }
}

// ================= split-bf16 mma.sync GEMM machinery =========================
#define TILE_ELEMS (128*40)            // 5120 bf16
#define STAGE_ELEMS (4*TILE_ELEMS)     // 20480
#define SMEM_MMA_BYTES (2*STAGE_ELEMS*2)  // 81920

__device__ __forceinline__ void mma16816(float* c, const uint32_t* a, const uint32_t* b) {
    asm volatile("mma.sync.aligned.m16n8k16.row.col.f32.bf16.bf16.f32 "
        "{%0,%1,%2,%3}, {%4,%5,%6,%7}, {%8,%9}, {%0,%1,%2,%3};"
        : "+f"(c[0]), "+f"(c[1]), "+f"(c[2]), "+f"(c[3])
        : "r"(a[0]), "r"(a[1]), "r"(a[2]), "r"(a[3]), "r"(b[0]), "r"(b[1]));
}

__device__ __forceinline__ void gemm_split(
    const __nv_bfloat16* __restrict__ Ahi, const __nv_bfloat16* __restrict__ Alo,
    size_t rA, int strdA,
    const __nv_bfloat16* __restrict__ Bhi, const __nv_bfloat16* __restrict__ Blo,
    size_t rB, int strdB,
    int nch, __nv_bfloat16* sm, float acc[4][4][4])
{
    const int tid = threadIdx.x;
    const int lane = tid & 31, gid = lane >> 2, tg = lane & 3;
    const int wid = tid >> 5;
    const int wm = (wid >> 2) * 64, wn = (wid & 3) * 32;
    const int lr = tid >> 2, lc = (tid & 3) * 8;

    uint4 pr[8];
    #pragma unroll
    for (int l = 0; l < 2; l++) {
        int r = lr + l*64;
        size_t oa = (rA + r) * (size_t)strdA + lc;
        size_t ob = (rB + r) * (size_t)strdB + lc;
        pr[l*4+0] = *(const uint4*)(Ahi + oa);
        pr[l*4+1] = *(const uint4*)(Alo + oa);
        pr[l*4+2] = *(const uint4*)(Bhi + ob);
        pr[l*4+3] = *(const uint4*)(Blo + ob);
    }
    #pragma unroll
    for (int l = 0; l < 2; l++) {
        int r = lr + l*64;
        __nv_bfloat16* base = sm + r*40 + lc;
        *(uint4*)(base)                = pr[l*4+0];
        *(uint4*)(base + TILE_ELEMS)   = pr[l*4+1];
        *(uint4*)(base + 2*TILE_ELEMS) = pr[l*4+2];
        *(uint4*)(base + 3*TILE_ELEMS) = pr[l*4+3];
    }
    __syncthreads();

    for (int ch = 0; ch < nch; ch++) {
        int s = ch & 1;
        bool nxt = (ch + 1) < nch;
        if (nxt) {
            int k0 = (ch + 1) * 32;
            #pragma unroll
            for (int l = 0; l < 2; l++) {
                int r = lr + l*64;
                size_t oa = (rA + r) * (size_t)strdA + k0 + lc;
                size_t ob = (rB + r) * (size_t)strdB + k0 + lc;
                pr[l*4+0] = *(const uint4*)(Ahi + oa);
                pr[l*4+1] = *(const uint4*)(Alo + oa);
                pr[l*4+2] = *(const uint4*)(Bhi + ob);
                pr[l*4+3] = *(const uint4*)(Blo + ob);
            }
        }
        {
            const __nv_bfloat16* sAhi = sm + s*STAGE_ELEMS;
            const __nv_bfloat16* sAlo = sAhi + TILE_ELEMS;
            const __nv_bfloat16* sBhi = sAhi + 2*TILE_ELEMS;
            const __nv_bfloat16* sBlo = sAhi + 3*TILE_ELEMS;
            #pragma unroll
            for (int ks = 0; ks < 2; ks++) {
                int kof = ks*16 + tg*2;
                uint32_t af[4][4], bh[4][2], bl[4][2];
                #pragma unroll
                for (int m = 0; m < 4; m++) {
                    const __nv_bfloat16* p = sAhi + (wm + m*16 + gid)*40 + kof;
                    af[m][0] = *(const uint32_t*)p;
                    af[m][1] = *(const uint32_t*)(p + 320);
                    af[m][2] = *(const uint32_t*)(p + 8);
                    af[m][3] = *(const uint32_t*)(p + 328);
                }
                #pragma unroll
                for (int n = 0; n < 4; n++) {
                    const __nv_bfloat16* p = sBhi + (wn + n*8 + gid)*40 + kof;
                    bh[n][0] = *(const uint32_t*)p;
                    bh[n][1] = *(const uint32_t*)(p + 8);
                    const __nv_bfloat16* q = sBlo + (wn + n*8 + gid)*40 + kof;
                    bl[n][0] = *(const uint32_t*)q;
                    bl[n][1] = *(const uint32_t*)(q + 8);
                }
                #pragma unroll
                for (int m = 0; m < 4; m++)
                    #pragma unroll
                    for (int n = 0; n < 4; n++)
                        mma16816(acc[m][n], af[m], bh[n]);   // hi*hi
                #pragma unroll
                for (int m = 0; m < 4; m++)
                    #pragma unroll
                    for (int n = 0; n < 4; n++)
                        mma16816(acc[m][n], af[m], bl[n]);   // hi*lo
                #pragma unroll
                for (int m = 0; m < 4; m++) {
                    const __nv_bfloat16* p = sAlo + (wm + m*16 + gid)*40 + kof;
                    af[m][0] = *(const uint32_t*)p;
                    af[m][1] = *(const uint32_t*)(p + 320);
                    af[m][2] = *(const uint32_t*)(p + 8);
                    af[m][3] = *(const uint32_t*)(p + 328);
                }
                #pragma unroll
                for (int m = 0; m < 4; m++)
                    #pragma unroll
                    for (int n = 0; n < 4; n++)
                        mma16816(acc[m][n], af[m], bh[n]);   // lo*hi
            }
        }
        if (nxt) {
            int so = (s ^ 1) * STAGE_ELEMS;
            #pragma unroll
            for (int l = 0; l < 2; l++) {
                int r = lr + l*64;
                __nv_bfloat16* base = sm + so + r*40 + lc;
                *(uint4*)(base)                = pr[l*4+0];
                *(uint4*)(base + TILE_ELEMS)   = pr[l*4+1];
                *(uint4*)(base + 2*TILE_ELEMS) = pr[l*4+2];
                *(uint4*)(base + 3*TILE_ELEMS) = pr[l*4+3];
            }
        }
        __syncthreads();
    }
}

// ================ scores = (q@k^T)*SCALE with causal mask (mma.sync) ==========
__global__ void __launch_bounds__(256) scores_mma_kernel() {
    int row0 = blockIdx.y * 128, col0 = blockIdx.x * 128;
    if (col0 > row0) return;
    int b = blockIdx.z;
    extern __shared__ __nv_bfloat16 sm[];
    float acc[4][4][4] = {};
    gemm_split(g_qhi, g_qlo, (size_t)b*SS + row0, DD,
               g_khi, g_klo, (size_t)b*SS + col0, DD,
               DD/32, sm, acc);

    const int tid = threadIdx.x;
    const int lane = tid & 31, gid = lane >> 2, tg = lane & 3;
    const int wid = tid >> 5;
    const int wm = (wid >> 2) * 64, wn = (wid & 3) * 32;
    const float NEG_INF = __int_as_float(0xff800000);
    bool diag = (col0 == row0);
    #pragma unroll
    for (int m = 0; m < 4; m++) {
        #pragma unroll
        for (int h = 0; h < 2; h++) {
            int i = row0 + wm + m*16 + gid + h*8;
            float* prow = g_scores + ((size_t)b*SS + i) * SS;
            #pragma unroll
            for (int n = 0; n < 4; n++) {
                int j = col0 + wn + n*8 + tg*2;
                float2 v;
                v.x = acc[m][n][h*2+0] * SCORE_SCALE;
                v.y = acc[m][n][h*2+1] * SCORE_SCALE;
                if (diag) {
                    if (j > i)   v.x = NEG_INF;
                    if (j+1 > i) v.y = NEG_INF;
                }
                *(float2*)(prow + j) = v;
            }
        }
    }
}

// ---------------- row softmax (smem) -> attn hi/lo bf16 ----------------
__global__ void softmax_kernel() {
    __shared__ float buf[SS];
    __shared__ float red[256];
    size_t row = blockIdx.x;
    int ri = (int)(row & (SS - 1));
    int jend = (ri & ~127) + 128;
    const float* p = g_scores + row * SS;
    __nv_bfloat16* ph = g_ahi + row * SS;
    __nv_bfloat16* pl = g_alo + row * SS;
    int t = threadIdx.x;
    float m = __int_as_float(0xff800000);
    for (int j = t; j < jend; j += 256) {
        float v = p[j];
        buf[j] = v;
        m = fmaxf(m, v);
    }
    red[t] = m; __syncthreads();
    for (int o = 128; o > 0; o >>= 1) {
        if (t < o) red[t] = fmaxf(red[t], red[t + o]);
        __syncthreads();
    }
    float mx = red[0];
    __syncthreads();
    float s = 0.f;
    for (int j = t; j < jend; j += 256) {
        float e = expf(buf[j] - mx);
        buf[j] = e;
        s += e;
    }
    red[t] = s; __syncthreads();
    for (int o = 128; o > 0; o >>= 1) {
        if (t < o) red[t] += red[t + o];
        __syncthreads();
    }
    float inv = 1.0f / red[0];
    for (int j = t; j < jend; j += 256) {
        float v = buf[j] * inv;
        __nv_bfloat16 h = __float2bfloat16(v);
        ph[j] = h;
        pl[j] = __float2bfloat16(v - __bfloat162float(h));
    }
}

// ================ out = attn @ v (NT vs vt, mma.sync) =========================
__global__ void __launch_bounds__(256) av_mma_kernel(float* __restrict__ out) {
    int col0 = blockIdx.x * 128;
    int row0 = blockIdx.y * 128;
    int b = blockIdx.z;
    extern __shared__ __nv_bfloat16 sm[];
    float acc[4][4][4] = {};
    int nch = (row0 >> 5) + 4;
    gemm_split(g_ahi, g_alo, (size_t)b*SS + row0, SS,
               g_vthi, g_vtlo, (size_t)b*DD + col0, SS,
               nch, sm, acc);

    const int tid = threadIdx.x;
    const int lane = tid & 31, gid = lane >> 2, tg = lane & 3;
    const int wid = tid >> 5;
    const int wm = (wid >> 2) * 64, wn = (wid & 3) * 32;
    #pragma unroll
    for (int m = 0; m < 4; m++) {
        #pragma unroll
        for (int h = 0; h < 2; h++) {
            int i = row0 + wm + m*16 + gid + h*8;
            float* prow = out + ((size_t)b*SS + i) * DD;
            #pragma unroll
            for (int n = 0; n < 4; n++) {
                int j = col0 + wn + n*8 + tg*2;
                float2 v;
                v.x = acc[m][n][h*2+0];
                v.y = acc[m][n][h*2+1];
                *(float2*)(prow + j) = v;
            }
        }
    }
}

// ---------------- launch ----------------
extern "C" void kernel_launch(void* const* d_in, const int* in_sizes, int n_in,
                              void* d_out, int out_size) {
    (void)in_sizes; (void)n_in; (void)out_size;
    const float* x  = (const float*)d_in[0];
    const float* Wq = (const float*)d_in[1];
    const float* Wk = (const float*)d_in[2];
    const float* Wv = (const float*)d_in[3];
    float* out = (float*)d_out;

    static int smem_set = 0;
    if (!smem_set) {
        cudaFuncSetAttribute(scores_mma_kernel, cudaFuncAttributeMaxDynamicSharedMemorySize, SMEM_MMA_BYTES);
        cudaFuncSetAttribute(av_mma_kernel,     cudaFuncAttributeMaxDynamicSharedMemorySize, SMEM_MMA_BYTES);
        smem_set = 1;
    }

    wmean_kernel<<<3, 256>>>(Wq, Wk, Wv);
    wquant_kernel<<<(3*DD*KW + 255)/256, 256>>>(Wq, Wk, Wv);
    actquant_kernel<<<MM, 128>>>(x);

    dim3 gqkv(DD/128, MM/128, 3);
    qkv_imma_kernel<<<gqkv, 256>>>();

    dim3 gvt(DD/32, SS/32, BB);
    vtrans_kernel<<<gvt, dim3(32, 8)>>>();

    dim3 gsc(SS/128, SS/128, BB);
    scores_mma_kernel<<<gsc, 256, SMEM_MMA_BYTES>>>();

    softmax_kernel<<<MM, 256>>>();

    dim3 gav(DD/128, SS/128, BB);
    av_mma_kernel<<<gav, 256, SMEM_MMA_BYTES>>>(out);
}

// round 13
// speedup vs baseline: 2.9813x; 1.0885x over previous
#include <cuda_runtime.h>
#include <cuda_bf16.h>
#include <math.h>
#include <stdint.h>

// Problem constants: B=8, S=2048, D=512
#define BB 8
#define SS 2048
#define DD 512
#define MM (BB*SS)
#define EPS_Q 1e-5f
#define SCORE_SCALE 0.35355339059327373f   // 8^-0.5

// ---------------- scratch ----------------
__device__ float g_wmean[3];
__device__ __nv_bfloat16 g_wbf[3][DD*DD];            // ternary weights as bf16 (exact)
__device__ __nv_bfloat16 g_xbf[MM*DD];               // int8-quantized activations as bf16 (exact)
__device__ float g_xscale[MM];
__device__ __nv_bfloat16 g_qhi[MM*DD];
__device__ __nv_bfloat16 g_qlo[MM*DD];
__device__ __nv_bfloat16 g_khi[MM*DD];
__device__ __nv_bfloat16 g_klo[MM*DD];
__device__ float g_v[MM*DD];
__device__ __nv_bfloat16 g_vthi[(size_t)BB*DD*SS];   // [b][d][j]
__device__ __nv_bfloat16 g_vtlo[(size_t)BB*DD*SS];
__device__ float g_scores[(size_t)BB*SS*SS];          // fp32 logits
__device__ __nv_bfloat16 g_ahi[(size_t)BB*SS*SS];
__device__ __nv_bfloat16 g_alo[(size_t)BB*SS*SS];

// ---------------- weight mean(|w|) ----------------
__global__ void wmean_kernel(const float* __restrict__ Wq,
                             const float* __restrict__ Wk,
                             const float* __restrict__ Wv) {
    const float* W = (blockIdx.x == 0) ? Wq : (blockIdx.x == 1) ? Wk : Wv;
    __shared__ float red[256];
    float s = 0.f;
    for (int i = threadIdx.x; i < DD*DD; i += 256) s += fabsf(W[i]);
    red[threadIdx.x] = s;
    __syncthreads();
    for (int o = 128; o > 0; o >>= 1) {
        if (threadIdx.x < o) red[threadIdx.x] += red[threadIdx.x + o];
        __syncthreads();
    }
    if (threadIdx.x == 0)
        g_wmean[blockIdx.x] = fmaxf(red[0] / (float)(DD*DD), EPS_Q);
}

// ---------------- weight ternary quant -> bf16 (exact) ----------------
__global__ void wquant_kernel(const float* __restrict__ Wq,
                              const float* __restrict__ Wk,
                              const float* __restrict__ Wv) {
    int i = blockIdx.x * blockDim.x + threadIdx.x;    // 4-elem group index
    if (i >= 3*DD*DD/4) return;
    int w = i / (DD*DD/4), j = i - w*(DD*DD/4);
    const float* W = (w == 0) ? Wq : (w == 1) ? Wk : Wv;
    float inv = 1.0f / g_wmean[w];
    float4 v = *(const float4*)(W + j*4);
    __align__(8) __nv_bfloat16 t[4];
    t[0] = __float2bfloat16(fminf(fmaxf(rintf(v.x*inv), -1.f), 1.f));
    t[1] = __float2bfloat16(fminf(fmaxf(rintf(v.y*inv), -1.f), 1.f));
    t[2] = __float2bfloat16(fminf(fmaxf(rintf(v.z*inv), -1.f), 1.f));
    t[3] = __float2bfloat16(fminf(fmaxf(rintf(v.w*inv), -1.f), 1.f));
    *(uint2*)(g_wbf[w] + j*4) = *(const uint2*)t;
}

// ---------------- activation per-token int8 quant -> bf16 (exact) -------------
__global__ void actquant_kernel(const float* __restrict__ x) {
    int row = blockIdx.x;
    int t = threadIdx.x;
    float4 v = ((const float4*)(x + (size_t)row * DD))[t];
    float m = fmaxf(fmaxf(fabsf(v.x), fabsf(v.y)), fmaxf(fabsf(v.z), fabsf(v.w)));
    __shared__ float red[128];
    red[t] = m; __syncthreads();
    for (int o = 64; o > 0; o >>= 1) {
        if (t < o) red[t] = fmaxf(red[t], red[t + o]);
        __syncthreads();
    }
    float mx = fmaxf(red[0], EPS_Q);
    float scale = 127.0f / mx;
    __align__(8) __nv_bfloat16 q[4];
    q[0] = __float2bfloat16(fminf(fmaxf(rintf(v.x*scale), -128.f), 127.f));
    q[1] = __float2bfloat16(fminf(fmaxf(rintf(v.y*scale), -128.f), 127.f));
    q[2] = __float2bfloat16(fminf(fmaxf(rintf(v.z*scale), -128.f), 127.f));
    q[3] = __float2bfloat16(fminf(fmaxf(rintf(v.w*scale), -128.f), 127.f));
    *(uint2*)(g_xbf + (size_t)row*DD + t*4) = *(const uint2*)q;
    if (t == 0) g_xscale[row] = mx / 127.0f;
}

// ================= bf16 mma common =============================================
#define TILE_ELEMS (128*40)            // 5120 bf16
#define SMEM_MMA_BYTES (2*4*TILE_ELEMS*2)  // 81920 (split kernels)

__device__ __forceinline__ void mma16816(float* c, const uint32_t* a, const uint32_t* b) {
    asm volatile("mma.sync.aligned.m16n8k16.row.col.f32.bf16.bf16.f32 "
        "{%0,%1,%2,%3}, {%4,%5,%6,%7}, {%8,%9}, {%0,%1,%2,%3};"
        : "+f"(c[0]), "+f"(c[1]), "+f"(c[2]), "+f"(c[3])
        : "r"(a[0]), "r"(a[1]), "r"(a[2]), "r"(a[3]), "r"(b[0]), "r"(b[1]));
}

// ================= QKV: single-term bf16 HMMA (exact int math) ================
// CTA 128x128, 8 warps (2x4), warp 64x32, k-chunk 32, double-buffered.
__global__ void __launch_bounds__(256) qkv_bf16_kernel() {
    __shared__ __nv_bfloat16 sA[2][TILE_ELEMS];
    __shared__ __nv_bfloat16 sB[2][TILE_ELEMS];
    int w = blockIdx.z;
    const __nv_bfloat16* A = g_xbf;
    const __nv_bfloat16* B = g_wbf[w];
    int row0 = blockIdx.y * 128, col0 = blockIdx.x * 128;
    const int tid = threadIdx.x;
    const int lane = tid & 31, gid = lane >> 2, tg = lane & 3;
    const int wid = tid >> 5;
    const int wm = (wid >> 2) * 64, wn = (wid & 3) * 32;
    const int lr = tid >> 2, lc = (tid & 3) * 8;
    float acc[4][4][4] = {};

    uint4 pa[2], pb[2];
    #pragma unroll
    for (int l = 0; l < 2; l++) {
        int r = lr + l*64;
        pa[l] = *(const uint4*)(A + (size_t)(row0 + r) * DD + lc);
        pb[l] = *(const uint4*)(B + (size_t)(col0 + r) * DD + lc);
    }
    #pragma unroll
    for (int l = 0; l < 2; l++) {
        int r = lr + l*64;
        *(uint4*)(sA[0] + r*40 + lc) = pa[l];
        *(uint4*)(sB[0] + r*40 + lc) = pb[l];
    }
    __syncthreads();

    for (int ch = 0; ch < 16; ch++) {
        int s = ch & 1;
        bool nxt = (ch + 1) < 16;
        if (nxt) {
            int k0 = (ch + 1) * 32;
            #pragma unroll
            for (int l = 0; l < 2; l++) {
                int r = lr + l*64;
                pa[l] = *(const uint4*)(A + (size_t)(row0 + r) * DD + k0 + lc);
                pb[l] = *(const uint4*)(B + (size_t)(col0 + r) * DD + k0 + lc);
            }
        }
        #pragma unroll
        for (int ks = 0; ks < 2; ks++) {
            int kof = ks*16 + tg*2;
            uint32_t af[4][4], bf[4][2];
            #pragma unroll
            for (int m = 0; m < 4; m++) {
                const __nv_bfloat16* p = sA[s] + (wm + m*16 + gid)*40 + kof;
                af[m][0] = *(const uint32_t*)p;
                af[m][1] = *(const uint32_t*)(p + 320);
                af[m][2] = *(const uint32_t*)(p + 8);
                af[m][3] = *(const uint32_t*)(p + 328);
            }
            #pragma unroll
            for (int n = 0; n < 4; n++) {
                const __nv_bfloat16* p = sB[s] + (wn + n*8 + gid)*40 + kof;
                bf[n][0] = *(const uint32_t*)p;
                bf[n][1] = *(const uint32_t*)(p + 8);
            }
            #pragma unroll
            for (int m = 0; m < 4; m++)
                #pragma unroll
                for (int n = 0; n < 4; n++)
                    mma16816(acc[m][n], af[m], bf[n]);
        }
        if (nxt) {
            #pragma unroll
            for (int l = 0; l < 2; l++) {
                int r = lr + l*64;
                *(uint4*)(sA[s^1] + r*40 + lc) = pa[l];
                *(uint4*)(sB[s^1] + r*40 + lc) = pb[l];
            }
        }
        __syncthreads();
    }

    float wmv = g_wmean[w];
    #pragma unroll
    for (int m = 0; m < 4; m++) {
        #pragma unroll
        for (int h = 0; h < 2; h++) {
            int i = row0 + wm + m*16 + gid + h*8;
            float sc = g_xscale[i] * wmv;
            if (w == 2) {
                float* prow = g_v + (size_t)i * DD;
                #pragma unroll
                for (int n = 0; n < 4; n++) {
                    int j = col0 + wn + n*8 + tg*2;
                    float2 v;
                    v.x = acc[m][n][h*2+0] * sc;
                    v.y = acc[m][n][h*2+1] * sc;
                    *(float2*)(prow + j) = v;
                }
            } else {
                __nv_bfloat16* ph = ((w == 0) ? g_qhi : g_khi) + (size_t)i * DD;
                __nv_bfloat16* pl = ((w == 0) ? g_qlo : g_klo) + (size_t)i * DD;
                #pragma unroll
                for (int n = 0; n < 4; n++) {
                    int j = col0 + wn + n*8 + tg*2;
                    float v0 = acc[m][n][h*2+0] * sc;
                    float v1 = acc[m][n][h*2+1] * sc;
                    __nv_bfloat16 h0 = __float2bfloat16(v0);
                    __nv_bfloat16 h1 = __float2bfloat16(v1);
                    __nv_bfloat162 hh; hh.x = h0; hh.y = h1;
                    __nv_bfloat162 ll;
                    ll.x = __float2bfloat16(v0 - __bfloat162float(h0));
                    ll.y = __float2bfloat16(v1 - __bfloat162float(h1));
                    *(__nv_bfloat162*)(ph + j) = hh;
                    *(__nv_bfloat162*)(pl + j) = ll;
                }
            }
        }
    }
}

// ---------------- transpose v -> vt hi/lo bf16 ----------------
__global__ void vtrans_kernel() {
    __shared__ float t[32][33];
    int b = blockIdx.z, d0 = blockIdx.x*32, j0 = blockIdx.y*32;
    int tx = threadIdx.x, ty = threadIdx.y;    // 32 x 8
    #pragma unroll
    for (int l = 0; l < 4; l++) {
        int j = ty + l*8;
        t[j][tx] = g_v[((size_t)b*SS + j0 + j) * DD + d0 + tx];
    }
    __syncthreads();
    #pragma unroll
    for (int l = 0; l < 4; l++) {
        int d = ty + l*8;
        float v = t[tx][d];
        __nv_bfloat16 h = __float2bfloat16(v);
        size_t o = ((size_t)b*DD + d0 + d) * SS + j0 + tx;
        g_vthi[o] = h;
        g_vtlo[o] = __float2bfloat16(v - __bfloat162float(h));
    }
}

// ================= split-bf16 gemm (3-term Markidis) ==========================
#define STAGE_ELEMS (4*TILE_ELEMS)     // 20480

__device__ __forceinline__ void gemm_split(
    const __nv_bfloat16* __restrict__ Ahi, const __nv_bfloat16* __restrict__ Alo,
    size_t rA, int strdA,
    const __nv_bfloat16* __restrict__ Bhi, const __nv_bfloat16* __restrict__ Blo,
    size_t rB, int strdB,
    int nch, __nv_bfloat16* sm, float acc[4][4][4])
{
    const int tid = threadIdx.x;
    const int lane = tid & 31, gid = lane >> 2, tg = lane & 3;
    const int wid = tid >> 5;
    const int wm = (wid >> 2) * 64, wn = (wid & 3) * 32;
    const int lr = tid >> 2, lc = (tid & 3) * 8;

    uint4 pr[8];
    #pragma unroll
    for (int l = 0; l < 2; l++) {
        int r = lr + l*64;
        size_t oa = (rA + r) * (size_t)strdA + lc;
        size_t ob = (rB + r) * (size_t)strdB + lc;
        pr[l*4+0] = *(const uint4*)(Ahi + oa);
        pr[l*4+1] = *(const uint4*)(Alo + oa);
        pr[l*4+2] = *(const uint4*)(Bhi + ob);
        pr[l*4+3] = *(const uint4*)(Blo + ob);
    }
    #pragma unroll
    for (int l = 0; l < 2; l++) {
        int r = lr + l*64;
        __nv_bfloat16* base = sm + r*40 + lc;
        *(uint4*)(base)                = pr[l*4+0];
        *(uint4*)(base + TILE_ELEMS)   = pr[l*4+1];
        *(uint4*)(base + 2*TILE_ELEMS) = pr[l*4+2];
        *(uint4*)(base + 3*TILE_ELEMS) = pr[l*4+3];
    }
    __syncthreads();

    for (int ch = 0; ch < nch; ch++) {
        int s = ch & 1;
        bool nxt = (ch + 1) < nch;
        if (nxt) {
            int k0 = (ch + 1) * 32;
            #pragma unroll
            for (int l = 0; l < 2; l++) {
                int r = lr + l*64;
                size_t oa = (rA + r) * (size_t)strdA + k0 + lc;
                size_t ob = (rB + r) * (size_t)strdB + k0 + lc;
                pr[l*4+0] = *(const uint4*)(Ahi + oa);
                pr[l*4+1] = *(const uint4*)(Alo + oa);
                pr[l*4+2] = *(const uint4*)(Bhi + ob);
                pr[l*4+3] = *(const uint4*)(Blo + ob);
            }
        }
        {
            const __nv_bfloat16* sAhi = sm + s*STAGE_ELEMS;
            const __nv_bfloat16* sAlo = sAhi + TILE_ELEMS;
            const __nv_bfloat16* sBhi = sAhi + 2*TILE_ELEMS;
            const __nv_bfloat16* sBlo = sAhi + 3*TILE_ELEMS;
            #pragma unroll
            for (int ks = 0; ks < 2; ks++) {
                int kof = ks*16 + tg*2;
                uint32_t af[4][4], bh[4][2], bl[4][2];
                #pragma unroll
                for (int m = 0; m < 4; m++) {
                    const __nv_bfloat16* p = sAhi + (wm + m*16 + gid)*40 + kof;
                    af[m][0] = *(const uint32_t*)p;
                    af[m][1] = *(const uint32_t*)(p + 320);
                    af[m][2] = *(const uint32_t*)(p + 8);
                    af[m][3] = *(const uint32_t*)(p + 328);
                }
                #pragma unroll
                for (int n = 0; n < 4; n++) {
                    const __nv_bfloat16* p = sBhi + (wn + n*8 + gid)*40 + kof;
                    bh[n][0] = *(const uint32_t*)p;
                    bh[n][1] = *(const uint32_t*)(p + 8);
                    const __nv_bfloat16* q = sBlo + (wn + n*8 + gid)*40 + kof;
                    bl[n][0] = *(const uint32_t*)q;
                    bl[n][1] = *(const uint32_t*)(q + 8);
                }
                #pragma unroll
                for (int m = 0; m < 4; m++)
                    #pragma unroll
                    for (int n = 0; n < 4; n++)
                        mma16816(acc[m][n], af[m], bh[n]);   // hi*hi
                #pragma unroll
                for (int m = 0; m < 4; m++)
                    #pragma unroll
                    for (int n = 0; n < 4; n++)
                        mma16816(acc[m][n], af[m], bl[n]);   // hi*lo
                #pragma unroll
                for (int m = 0; m < 4; m++) {
                    const __nv_bfloat16* p = sAlo + (wm + m*16 + gid)*40 + kof;
                    af[m][0] = *(const uint32_t*)p;
                    af[m][1] = *(const uint32_t*)(p + 320);
                    af[m][2] = *(const uint32_t*)(p + 8);
                    af[m][3] = *(const uint32_t*)(p + 328);
                }
                #pragma unroll
                for (int m = 0; m < 4; m++)
                    #pragma unroll
                    for (int n = 0; n < 4; n++)
                        mma16816(acc[m][n], af[m], bh[n]);   // lo*hi
            }
        }
        if (nxt) {
            int so = (s ^ 1) * STAGE_ELEMS;
            #pragma unroll
            for (int l = 0; l < 2; l++) {
                int r = lr + l*64;
                __nv_bfloat16* base = sm + so + r*40 + lc;
                *(uint4*)(base)                = pr[l*4+0];
                *(uint4*)(base + TILE_ELEMS)   = pr[l*4+1];
                *(uint4*)(base + 2*TILE_ELEMS) = pr[l*4+2];
                *(uint4*)(base + 3*TILE_ELEMS) = pr[l*4+3];
            }
        }
        __syncthreads();
    }
}

// ================ scores = (q@k^T)*SCALE with causal mask =====================
__global__ void __launch_bounds__(256) scores_mma_kernel() {
    int row0 = blockIdx.y * 128, col0 = blockIdx.x * 128;
    if (col0 > row0) return;
    int b = blockIdx.z;
    extern __shared__ __nv_bfloat16 sm[];
    float acc[4][4][4] = {};
    gemm_split(g_qhi, g_qlo, (size_t)b*SS + row0, DD,
               g_khi, g_klo, (size_t)b*SS + col0, DD,
               DD/32, sm, acc);

    const int tid = threadIdx.x;
    const int lane = tid & 31, gid = lane >> 2, tg = lane & 3;
    const int wid = tid >> 5;
    const int wm = (wid >> 2) * 64, wn = (wid & 3) * 32;
    const float NEG_INF = __int_as_float(0xff800000);
    bool diag = (col0 == row0);
    #pragma unroll
    for (int m = 0; m < 4; m++) {
        #pragma unroll
        for (int h = 0; h < 2; h++) {
            int i = row0 + wm + m*16 + gid + h*8;
            float* prow = g_scores + ((size_t)b*SS + i) * SS;
            #pragma unroll
            for (int n = 0; n < 4; n++) {
                int j = col0 + wn + n*8 + tg*2;
                float2 v;
                v.x = acc[m][n][h*2+0] * SCORE_SCALE;
                v.y = acc[m][n][h*2+1] * SCORE_SCALE;
                if (diag) {
                    if (j > i)   v.x = NEG_INF;
                    if (j+1 > i) v.y = NEG_INF;
                }
                *(float2*)(prow + j) = v;
            }
        }
    }
}

// ---------------- row softmax (smem) -> attn hi/lo bf16 ----------------
__global__ void softmax_kernel() {
    __shared__ float buf[SS];
    __shared__ float red[256];
    size_t row = blockIdx.x;
    int ri = (int)(row & (SS - 1));
    int jend = (ri & ~127) + 128;
    const float* p = g_scores + row * SS;
    __nv_bfloat16* ph = g_ahi + row * SS;
    __nv_bfloat16* pl = g_alo + row * SS;
    int t = threadIdx.x;
    float m = __int_as_float(0xff800000);
    for (int j = t; j < jend; j += 256) {
        float v = p[j];
        buf[j] = v;
        m = fmaxf(m, v);
    }
    red[t] = m; __syncthreads();
    for (int o = 128; o > 0; o >>= 1) {
        if (t < o) red[t] = fmaxf(red[t], red[t + o]);
        __syncthreads();
    }
    float mx = red[0];
    __syncthreads();
    float s = 0.f;
    for (int j = t; j < jend; j += 256) {
        float e = expf(buf[j] - mx);
        buf[j] = e;
        s += e;
    }
    red[t] = s; __syncthreads();
    for (int o = 128; o > 0; o >>= 1) {
        if (t < o) red[t] += red[t + o];
        __syncthreads();
    }
    float inv = 1.0f / red[0];
    for (int j = t; j < jend; j += 256) {
        float v = buf[j] * inv;
        __nv_bfloat16 h = __float2bfloat16(v);
        ph[j] = h;
        pl[j] = __float2bfloat16(v - __bfloat162float(h));
    }
}

// ================ out = attn @ v (NT vs vt) ===================================
__global__ void __launch_bounds__(256) av_mma_kernel(float* __restrict__ out) {
    int col0 = blockIdx.x * 128;
    int row0 = blockIdx.y * 128;
    int b = blockIdx.z;
    extern __shared__ __nv_bfloat16 sm[];
    float acc[4][4][4] = {};
    int nch = (row0 >> 5) + 4;
    gemm_split(g_ahi, g_alo, (size_t)b*SS + row0, SS,
               g_vthi, g_vtlo, (size_t)b*DD + col0, SS,
               nch, sm, acc);

    const int tid = threadIdx.x;
    const int lane = tid & 31, gid = lane >> 2, tg = lane & 3;
    const int wid = tid >> 5;
    const int wm = (wid >> 2) * 64, wn = (wid & 3) * 32;
    #pragma unroll
    for (int m = 0; m < 4; m++) {
        #pragma unroll
        for (int h = 0; h < 2; h++) {
            int i = row0 + wm + m*16 + gid + h*8;
            float* prow = out + ((size_t)b*SS + i) * DD;
            #pragma unroll
            for (int n = 0; n < 4; n++) {
                int j = col0 + wn + n*8 + tg*2;
                float2 v;
                v.x = acc[m][n][h*2+0];
                v.y = acc[m][n][h*2+1];
                *(float2*)(prow + j) = v;
            }
        }
    }
}

// ---------------- launch ----------------
extern "C" void kernel_launch(void* const* d_in, const int* in_sizes, int n_in,
                              void* d_out, int out_size) {
    (void)in_sizes; (void)n_in; (void)out_size;
    const float* x  = (const float*)d_in[0];
    const float* Wq = (const float*)d_in[1];
    const float* Wk = (const float*)d_in[2];
    const float* Wv = (const float*)d_in[3];
    float* out = (float*)d_out;

    static int smem_set = 0;
    if (!smem_set) {
        cudaFuncSetAttribute(scores_mma_kernel, cudaFuncAttributeMaxDynamicSharedMemorySize, SMEM_MMA_BYTES);
        cudaFuncSetAttribute(av_mma_kernel,     cudaFuncAttributeMaxDynamicSharedMemorySize, SMEM_MMA_BYTES);
        smem_set = 1;
    }

    wmean_kernel<<<3, 256>>>(Wq, Wk, Wv);
    wquant_kernel<<<(3*DD*DD/4 + 255)/256, 256>>>(Wq, Wk, Wv);
    actquant_kernel<<<MM, 128>>>(x);

    dim3 gqkv(DD/128, MM/128, 3);
    qkv_bf16_kernel<<<gqkv, 256>>>();

    dim3 gvt(DD/32, SS/32, BB);
    vtrans_kernel<<<gvt, dim3(32, 8)>>>();

    dim3 gsc(SS/128, SS/128, BB);
    scores_mma_kernel<<<gsc, 256, SMEM_MMA_BYTES>>>();

    softmax_kernel<<<MM, 256>>>();

    dim3 gav(DD/128, SS/128, BB);
    av_mma_kernel<<<gav, 256, SMEM_MMA_BYTES>>>(out);
}

// round 16
// speedup vs baseline: 3.1134x; 1.0443x over previous
#include <cuda_runtime.h>
#include <cuda_bf16.h>
#include <math.h>
#include <stdint.h>

// Problem constants: B=8, S=2048, D=512
#define BB 8
#define SS 2048
#define DD 512
#define MM (BB*SS)
#define EPS_Q 1e-5f
#define SCORE_SCALE 0.35355339059327373f   // 8^-0.5

// ---------------- scratch ----------------
__device__ float g_wmean[3];
__device__ __nv_bfloat16 g_wbf[3][DD*DD];
__device__ __nv_bfloat16 g_xbf[MM*DD];
__device__ float g_xscale[MM];
__device__ __nv_bfloat16 g_qhi[MM*DD];
__device__ __nv_bfloat16 g_qlo[MM*DD];
__device__ __nv_bfloat16 g_khi[MM*DD];
__device__ __nv_bfloat16 g_klo[MM*DD];
__device__ float g_v[MM*DD];
__device__ __nv_bfloat16 g_vthi[(size_t)BB*DD*SS];   // [b][d][j]
__device__ __nv_bfloat16 g_vtlo[(size_t)BB*DD*SS];
__device__ float g_scores[(size_t)BB*SS*SS];
__device__ __nv_bfloat16 g_ahi[(size_t)BB*SS*SS];
__device__ __nv_bfloat16 g_alo[(size_t)BB*SS*SS];

// ---------------- cp.async helpers ----------------
#define CP16(dst_sm, src_g) \
    asm volatile("cp.async.cg.shared.global [%0], [%1], 16;" \
                 :: "r"(dst_sm), "l"(src_g) : "memory")
#define CP_COMMIT() asm volatile("cp.async.commit_group;" ::: "memory")
#define CP_WAIT0()  asm volatile("cp.async.wait_group 0;" ::: "memory")
#define CP_WAIT1()  asm volatile("cp.async.wait_group 1;" ::: "memory")

__device__ __forceinline__ uint32_t smaddr(const void* p) {
    return (uint32_t)__cvta_generic_to_shared(p);
}

// ---------------- weight mean(|w|) ----------------
__global__ void wmean_kernel(const float* __restrict__ Wq,
                             const float* __restrict__ Wk,
                             const float* __restrict__ Wv) {
    const float* W = (blockIdx.x == 0) ? Wq : (blockIdx.x == 1) ? Wk : Wv;
    __shared__ float red[256];
    float s = 0.f;
    for (int i = threadIdx.x; i < DD*DD; i += 256) s += fabsf(W[i]);
    red[threadIdx.x] = s;
    __syncthreads();
    for (int o = 128; o > 0; o >>= 1) {
        if (threadIdx.x < o) red[threadIdx.x] += red[threadIdx.x + o];
        __syncthreads();
    }
    if (threadIdx.x == 0)
        g_wmean[blockIdx.x] = fmaxf(red[0] / (float)(DD*DD), EPS_Q);
}

// ---------------- weight ternary quant -> bf16 (exact) ----------------
__global__ void wquant_kernel(const float* __restrict__ Wq,
                              const float* __restrict__ Wk,
                              const float* __restrict__ Wv) {
    int i = blockIdx.x * blockDim.x + threadIdx.x;
    if (i >= 3*DD*DD/4) return;
    int w = i / (DD*DD/4), j = i - w*(DD*DD/4);
    const float* W = (w == 0) ? Wq : (w == 1) ? Wk : Wv;
    float inv = 1.0f / g_wmean[w];
    float4 v = *(const float4*)(W + j*4);
    __align__(8) __nv_bfloat16 t[4];
    t[0] = __float2bfloat16(fminf(fmaxf(rintf(v.x*inv), -1.f), 1.f));
    t[1] = __float2bfloat16(fminf(fmaxf(rintf(v.y*inv), -1.f), 1.f));
    t[2] = __float2bfloat16(fminf(fmaxf(rintf(v.z*inv), -1.f), 1.f));
    t[3] = __float2bfloat16(fminf(fmaxf(rintf(v.w*inv), -1.f), 1.f));
    *(uint2*)(g_wbf[w] + j*4) = *(const uint2*)t;
}

// ---------------- activation per-token int8 quant -> bf16 (exact) -------------
__global__ void actquant_kernel(const float* __restrict__ x) {
    int row = blockIdx.x;
    int t = threadIdx.x;
    float4 v = ((const float4*)(x + (size_t)row * DD))[t];
    float m = fmaxf(fmaxf(fabsf(v.x), fabsf(v.y)), fmaxf(fabsf(v.z), fabsf(v.w)));
    __shared__ float red[128];
    red[t] = m; __syncthreads();
    for (int o = 64; o > 0; o >>= 1) {
        if (t < o) red[t] = fmaxf(red[t], red[t + o]);
        __syncthreads();
    }
    float mx = fmaxf(red[0], EPS_Q);
    float scale = 127.0f / mx;
    __align__(8) __nv_bfloat16 q[4];
    q[0] = __float2bfloat16(fminf(fmaxf(rintf(v.x*scale), -128.f), 127.f));
    q[1] = __float2bfloat16(fminf(fmaxf(rintf(v.y*scale), -128.f), 127.f));
    q[2] = __float2bfloat16(fminf(fmaxf(rintf(v.z*scale), -128.f), 127.f));
    q[3] = __float2bfloat16(fminf(fmaxf(rintf(v.w*scale), -128.f), 127.f));
    *(uint2*)(g_xbf + (size_t)row*DD + t*4) = *(const uint2*)q;
    if (t == 0) g_xscale[row] = mx / 127.0f;
}

// ================= bf16 mma ====================================================
__device__ __forceinline__ void mma16816(float* c, const uint32_t* a, const uint32_t* b) {
    asm volatile("mma.sync.aligned.m16n8k16.row.col.f32.bf16.bf16.f32 "
        "{%0,%1,%2,%3}, {%4,%5,%6,%7}, {%8,%9}, {%0,%1,%2,%3};"
        : "+f"(c[0]), "+f"(c[1]), "+f"(c[2]), "+f"(c[3])
        : "r"(a[0]), "r"(a[1]), "r"(a[2]), "r"(a[3]), "r"(b[0]), "r"(b[1]));
}

// ================= QKV: bf16 HMMA, k-chunk 64, 3-stage cp.async ================
#define QSTRIDE 72                        // elems per row (144B, 16B-multiple, conflict-free)
#define QTILE   (128*QSTRIDE)             // 9216 elems
#define QSMEM_BYTES (3*2*QTILE*2)         // 110592

__device__ __forceinline__ void qkv_issue(__nv_bfloat16* sm, int st,
                                          const __nv_bfloat16* A, const __nv_bfloat16* B,
                                          int row0, int col0, int k0, int tid) {
    __nv_bfloat16* dA = sm + st*2*QTILE;
    __nv_bfloat16* dB = dA + QTILE;
    #pragma unroll
    for (int l = 0; l < 4; l++) {
        int slot = tid + l*256, r = slot >> 3, c = slot & 7;
        CP16(smaddr(dA + r*QSTRIDE + c*8), A + (size_t)(row0 + r)*DD + k0 + c*8);
        CP16(smaddr(dB + r*QSTRIDE + c*8), B + (size_t)(col0 + r)*DD + k0 + c*8);
    }
    CP_COMMIT();
}

__global__ void __launch_bounds__(256) qkv_bf16_kernel() {
    extern __shared__ __nv_bfloat16 qsm[];
    int w = blockIdx.z;
    const __nv_bfloat16* A = g_xbf;
    const __nv_bfloat16* B = g_wbf[w];
    int row0 = blockIdx.y * 128, col0 = blockIdx.x * 128;
    const int tid = threadIdx.x;
    const int lane = tid & 31, gid = lane >> 2, tg = lane & 3;
    const int wid = tid >> 5;
    const int wm = (wid >> 2) * 64, wn = (wid & 3) * 32;
    float acc[4][4][4] = {};
    const int NCH = DD/64;     // 8

    qkv_issue(qsm, 0, A, B, row0, col0, 0, tid);
    qkv_issue(qsm, 1, A, B, row0, col0, 64, tid);

    for (int ch = 0; ch < NCH; ch++) {
        int st = ch % 3;
        if (ch + 1 < NCH) CP_WAIT1(); else CP_WAIT0();
        __syncthreads();
        const __nv_bfloat16* sA = qsm + st*2*QTILE;
        const __nv_bfloat16* sB = sA + QTILE;
        #pragma unroll
        for (int ks = 0; ks < 4; ks++) {
            int kof = ks*16 + tg*2;
            uint32_t af[4][4], bf[4][2];
            #pragma unroll
            for (int m = 0; m < 4; m++) {
                const __nv_bfloat16* p = sA + (wm + m*16 + gid)*QSTRIDE + kof;
                af[m][0] = *(const uint32_t*)p;
                af[m][1] = *(const uint32_t*)(p + 8*QSTRIDE);
                af[m][2] = *(const uint32_t*)(p + 8);
                af[m][3] = *(const uint32_t*)(p + 8*QSTRIDE + 8);
            }
            #pragma unroll
            for (int n = 0; n < 4; n++) {
                const __nv_bfloat16* p = sB + (wn + n*8 + gid)*QSTRIDE + kof;
                bf[n][0] = *(const uint32_t*)p;
                bf[n][1] = *(const uint32_t*)(p + 8);
            }
            #pragma unroll
            for (int m = 0; m < 4; m++)
                #pragma unroll
                for (int n = 0; n < 4; n++)
                    mma16816(acc[m][n], af[m], bf[n]);
        }
        if (ch + 2 < NCH)
            qkv_issue(qsm, (ch + 2) % 3, A, B, row0, col0, (ch + 2)*64, tid);
    }

    float wmv = g_wmean[w];
    #pragma unroll
    for (int m = 0; m < 4; m++) {
        #pragma unroll
        for (int h = 0; h < 2; h++) {
            int i = row0 + wm + m*16 + gid + h*8;
            float sc = g_xscale[i] * wmv;
            if (w == 2) {
                float* prow = g_v + (size_t)i * DD;
                #pragma unroll
                for (int n = 0; n < 4; n++) {
                    int j = col0 + wn + n*8 + tg*2;
                    float2 v;
                    v.x = acc[m][n][h*2+0] * sc;
                    v.y = acc[m][n][h*2+1] * sc;
                    *(float2*)(prow + j) = v;
                }
            } else {
                __nv_bfloat16* ph = ((w == 0) ? g_qhi : g_khi) + (size_t)i * DD;
                __nv_bfloat16* pl = ((w == 0) ? g_qlo : g_klo) + (size_t)i * DD;
                #pragma unroll
                for (int n = 0; n < 4; n++) {
                    int j = col0 + wn + n*8 + tg*2;
                    float v0 = acc[m][n][h*2+0] * sc;
                    float v1 = acc[m][n][h*2+1] * sc;
                    __nv_bfloat16 h0 = __float2bfloat16(v0);
                    __nv_bfloat16 h1 = __float2bfloat16(v1);
                    __nv_bfloat162 hh; hh.x = h0; hh.y = h1;
                    __nv_bfloat162 ll;
                    ll.x = __float2bfloat16(v0 - __bfloat162float(h0));
                    ll.y = __float2bfloat16(v1 - __bfloat162float(h1));
                    *(__nv_bfloat162*)(ph + j) = hh;
                    *(__nv_bfloat162*)(pl + j) = ll;
                }
            }
        }
    }
}

// ---------------- transpose v -> vt hi/lo bf16 ----------------
__global__ void vtrans_kernel() {
    __shared__ float t[32][33];
    int b = blockIdx.z, d0 = blockIdx.x*32, j0 = blockIdx.y*32;
    int tx = threadIdx.x, ty = threadIdx.y;    // 32 x 8
    #pragma unroll
    for (int l = 0; l < 4; l++) {
        int j = ty + l*8;
        t[j][tx] = g_v[((size_t)b*SS + j0 + j) * DD + d0 + tx];
    }
    __syncthreads();
    #pragma unroll
    for (int l = 0; l < 4; l++) {
        int d = ty + l*8;
        float v = t[tx][d];
        __nv_bfloat16 h = __float2bfloat16(v);
        size_t o = ((size_t)b*DD + d0 + d) * SS + j0 + tx;
        g_vthi[o] = h;
        g_vtlo[o] = __float2bfloat16(v - __bfloat162float(h));
    }
}

// ================= split-bf16 gemm (3-term), cp.async 2-stage ==================
#define TILE_ELEMS (128*40)
#define STAGE_ELEMS (4*TILE_ELEMS)
#define SMEM_MMA_BYTES (2*STAGE_ELEMS*2)   // 81920

__device__ __forceinline__ void split_issue(__nv_bfloat16* sm, int st,
    const __nv_bfloat16* Ahi, const __nv_bfloat16* Alo, size_t rA, int strdA,
    const __nv_bfloat16* Bhi, const __nv_bfloat16* Blo, size_t rB, int strdB,
    int k0, int tid)
{
    __nv_bfloat16* base = sm + st*STAGE_ELEMS;
    #pragma unroll
    for (int l = 0; l < 2; l++) {
        int slot = tid + l*256, r = slot >> 2, c = slot & 3;
        int doff = r*40 + c*8;
        size_t oa = (rA + r) * (size_t)strdA + k0 + c*8;
        size_t ob = (rB + r) * (size_t)strdB + k0 + c*8;
        CP16(smaddr(base + doff),                Ahi + oa);
        CP16(smaddr(base + TILE_ELEMS + doff),   Alo + oa);
        CP16(smaddr(base + 2*TILE_ELEMS + doff), Bhi + ob);
        CP16(smaddr(base + 3*TILE_ELEMS + doff), Blo + ob);
    }
    CP_COMMIT();
}

__device__ __forceinline__ void gemm_split(
    const __nv_bfloat16* __restrict__ Ahi, const __nv_bfloat16* __restrict__ Alo,
    size_t rA, int strdA,
    const __nv_bfloat16* __restrict__ Bhi, const __nv_bfloat16* __restrict__ Blo,
    size_t rB, int strdB,
    int nch, __nv_bfloat16* sm, float acc[4][4][4])
{
    const int tid = threadIdx.x;
    const int lane = tid & 31, gid = lane >> 2, tg = lane & 3;
    const int wid = tid >> 5;
    const int wm = (wid >> 2) * 64, wn = (wid & 3) * 32;

    split_issue(sm, 0, Ahi, Alo, rA, strdA, Bhi, Blo, rB, strdB, 0, tid);

    for (int ch = 0; ch < nch; ch++) {
        int s = ch & 1;
        bool nxt = (ch + 1) < nch;
        if (nxt)
            split_issue(sm, s^1, Ahi, Alo, rA, strdA, Bhi, Blo, rB, strdB, (ch+1)*32, tid);
        if (nxt) CP_WAIT1(); else CP_WAIT0();
        __syncthreads();
        {
            const __nv_bfloat16* sAhi = sm + s*STAGE_ELEMS;
            const __nv_bfloat16* sAlo = sAhi + TILE_ELEMS;
            const __nv_bfloat16* sBhi = sAhi + 2*TILE_ELEMS;
            const __nv_bfloat16* sBlo = sAhi + 3*TILE_ELEMS;
            #pragma unroll
            for (int ks = 0; ks < 2; ks++) {
                int kof = ks*16 + tg*2;
                uint32_t af[4][4], bh[4][2], bl[4][2];
                #pragma unroll
                for (int m = 0; m < 4; m++) {
                    const __nv_bfloat16* p = sAhi + (wm + m*16 + gid)*40 + kof;
                    af[m][0] = *(const uint32_t*)p;
                    af[m][1] = *(const uint32_t*)(p + 320);
                    af[m][2] = *(const uint32_t*)(p + 8);
                    af[m][3] = *(const uint32_t*)(p + 328);
                }
                #pragma unroll
                for (int n = 0; n < 4; n++) {
                    const __nv_bfloat16* p = sBhi + (wn + n*8 + gid)*40 + kof;
                    bh[n][0] = *(const uint32_t*)p;
                    bh[n][1] = *(const uint32_t*)(p + 8);
                    const __nv_bfloat16* q = sBlo + (wn + n*8 + gid)*40 + kof;
                    bl[n][0] = *(const uint32_t*)q;
                    bl[n][1] = *(const uint32_t*)(q + 8);
                }
                #pragma unroll
                for (int m = 0; m < 4; m++)
                    #pragma unroll
                    for (int n = 0; n < 4; n++)
                        mma16816(acc[m][n], af[m], bh[n]);   // hi*hi
                #pragma unroll
                for (int m = 0; m < 4; m++)
                    #pragma unroll
                    for (int n = 0; n < 4; n++)
                        mma16816(acc[m][n], af[m], bl[n]);   // hi*lo
                #pragma unroll
                for (int m = 0; m < 4; m++) {
                    const __nv_bfloat16* p = sAlo + (wm + m*16 + gid)*40 + kof;
                    af[m][0] = *(const uint32_t*)p;
                    af[m][1] = *(const uint32_t*)(p + 320);
                    af[m][2] = *(const uint32_t*)(p + 8);
                    af[m][3] = *(const uint32_t*)(p + 328);
                }
                #pragma unroll
                for (int m = 0; m < 4; m++)
                    #pragma unroll
                    for (int n = 0; n < 4; n++)
                        mma16816(acc[m][n], af[m], bh[n]);   // lo*hi
            }
        }
        __syncthreads();   // stage s will be refilled next iteration
    }
}

// ================ scores = (q@k^T)*SCALE with causal mask =====================
__global__ void __launch_bounds__(256) scores_mma_kernel() {
    int row0 = blockIdx.y * 128, col0 = blockIdx.x * 128;
    if (col0 > row0) return;
    int b = blockIdx.z;
    extern __shared__ __nv_bfloat16 sm[];
    float acc[4][4][4] = {};
    gemm_split(g_qhi, g_qlo, (size_t)b*SS + row0, DD,
               g_khi, g_klo, (size_t)b*SS + col0, DD,
               DD/32, sm, acc);

    const int tid = threadIdx.x;
    const int lane = tid & 31, gid = lane >> 2, tg = lane & 3;
    const int wid = tid >> 5;
    const int wm = (wid >> 2) * 64, wn = (wid & 3) * 32;
    const float NEG_INF = __int_as_float(0xff800000);
    bool diag = (col0 == row0);
    #pragma unroll
    for (int m = 0; m < 4; m++) {
        #pragma unroll
        for (int h = 0; h < 2; h++) {
            int i = row0 + wm + m*16 + gid + h*8;
            float* prow = g_scores + ((size_t)b*SS + i) * SS;
            #pragma unroll
            for (int n = 0; n < 4; n++) {
                int j = col0 + wn + n*8 + tg*2;
                float2 v;
                v.x = acc[m][n][h*2+0] * SCORE_SCALE;
                v.y = acc[m][n][h*2+1] * SCORE_SCALE;
                if (diag) {
                    if (j > i)   v.x = NEG_INF;
                    if (j+1 > i) v.y = NEG_INF;
                }
                *(float2*)(prow + j) = v;
            }
        }
    }
}

// ---------------- row softmax (smem) -> attn hi/lo bf16 ----------------
__global__ void softmax_kernel() {
    __shared__ float buf[SS];
    __shared__ float red[256];
    size_t row = blockIdx.x;
    int ri = (int)(row & (SS - 1));
    int jend = (ri & ~127) + 128;
    const float* p = g_scores + row * SS;
    __nv_bfloat16* ph = g_ahi + row * SS;
    __nv_bfloat16* pl = g_alo + row * SS;
    int t = threadIdx.x;
    float m = __int_as_float(0xff800000);
    for (int j = t; j < jend; j += 256) {
        float v = p[j];
        buf[j] = v;
        m = fmaxf(m, v);
    }
    red[t] = m; __syncthreads();
    for (int o = 128; o > 0; o >>= 1) {
        if (t < o) red[t] = fmaxf(red[t], red[t + o]);
        __syncthreads();
    }
    float mx = red[0];
    __syncthreads();
    float s = 0.f;
    for (int j = t; j < jend; j += 256) {
        float e = expf(buf[j] - mx);
        buf[j] = e;
        s += e;
    }
    red[t] = s; __syncthreads();
    for (int o = 128; o > 0; o >>= 1) {
        if (t < o) red[t] += red[t + o];
        __syncthreads();
    }
    float inv = 1.0f / red[0];
    for (int j = t; j < jend; j += 256) {
        float v = buf[j] * inv;
        __nv_bfloat16 h = __float2bfloat16(v);
        ph[j] = h;
        pl[j] = __float2bfloat16(v - __bfloat162float(h));
    }
}

// ================ out = attn @ v (NT vs vt) ===================================
__global__ void __launch_bounds__(256) av_mma_kernel(float* __restrict__ out) {
    int col0 = blockIdx.x * 128;
    int row0 = blockIdx.y * 128;
    int b = blockIdx.z;
    extern __shared__ __nv_bfloat16 sm[];
    float acc[4][4][4] = {};
    int nch = (row0 >> 5) + 4;
    gemm_split(g_ahi, g_alo, (size_t)b*SS + row0, SS,
               g_vthi, g_vtlo, (size_t)b*DD + col0, SS,
               nch, sm, acc);

    const int tid = threadIdx.x;
    const int lane = tid & 31, gid = lane >> 2, tg = lane & 3;
    const int wid = tid >> 5;
    const int wm = (wid >> 2) * 64, wn = (wid & 3) * 32;
    #pragma unroll
    for (int m = 0; m < 4; m++) {
        #pragma unroll
        for (int h = 0; h < 2; h++) {
            int i = row0 + wm + m*16 + gid + h*8;
            float* prow = out + ((size_t)b*SS + i) * DD;
            #pragma unroll
            for (int n = 0; n < 4; n++) {
                int j = col0 + wn + n*8 + tg*2;
                float2 v;
                v.x = acc[m][n][h*2+0];
                v.y = acc[m][n][h*2+1];
                *(float2*)(prow + j) = v;
            }
        }
    }
}

// ---------------- launch ----------------
extern "C" void kernel_launch(void* const* d_in, const int* in_sizes, int n_in,
                              void* d_out, int out_size) {
    (void)in_sizes; (void)n_in; (void)out_size;
    const float* x  = (const float*)d_in[0];
    const float* Wq = (const float*)d_in[1];
    const float* Wk = (const float*)d_in[2];
    const float* Wv = (const float*)d_in[3];
    float* out = (float*)d_out;

    static int smem_set = 0;
    if (!smem_set) {
        cudaFuncSetAttribute(qkv_bf16_kernel,   cudaFuncAttributeMaxDynamicSharedMemorySize, QSMEM_BYTES);
        cudaFuncSetAttribute(scores_mma_kernel, cudaFuncAttributeMaxDynamicSharedMemorySize, SMEM_MMA_BYTES);
        cudaFuncSetAttribute(av_mma_kernel,     cudaFuncAttributeMaxDynamicSharedMemorySize, SMEM_MMA_BYTES);
        smem_set = 1;
    }

    wmean_kernel<<<3, 256>>>(Wq, Wk, Wv);
    wquant_kernel<<<(3*DD*DD/4 + 255)/256, 256>>>(Wq, Wk, Wv);
    actquant_kernel<<<MM, 128>>>(x);

    dim3 gqkv(DD/128, MM/128, 3);
    qkv_bf16_kernel<<<gqkv, 256, QSMEM_BYTES>>>();

    dim3 gvt(DD/32, SS/32, BB);
    vtrans_kernel<<<gvt, dim3(32, 8)>>>();

    dim3 gsc(SS/128, SS/128, BB);
    scores_mma_kernel<<<gsc, 256, SMEM_MMA_BYTES>>>();

    softmax_kernel<<<MM, 256>>>();

    dim3 gav(DD/128, SS/128, BB);
    av_mma_kernel<<<gav, 256, SMEM_MMA_BYTES>>>(out);
}